// round 5
// baseline (speedup 1.0000x reference)
#include <cuda_runtime.h>
#include <cuda_bf16.h>
#include <math.h>
#include <stdint.h>

#define SLOPE 0.2f

// Shapes fixed: B=8, N=2048, D=128.
__device__ float g_h[8 * 2048 * 128];           // h = x @ W (fp32)
__device__ __nv_bfloat16 g_hT1[8 * 128 * 2048]; // hi bf16 of h, transposed [b][o][j]
__device__ __nv_bfloat16 g_hT2[8 * 128 * 2048]; // lo bf16 residual
__device__ float g_ssrc[8 * 2048];
__device__ float g_sdst[8 * 2048];
__device__ float g_v[8 * 2048];
__device__ int   g_perm[8 * 2048];
__device__ float g_w1[8 * 2048];
__device__ float g_w02[8 * 2048];
__device__ float g_suf1[8 * 2049 * 128];
__device__ float g_pre02[8 * 2049 * 128];
__device__ float g_sufD1[8 * 2049];
__device__ float g_preD02[8 * 2049];

// ---------------------------------------------------------------------------
// helpers (all sm_80-era: ldmatrix / cp.async / mma.sync — no 'a'-gated instrs)
// ---------------------------------------------------------------------------
__device__ __forceinline__ uint32_t smem_u32(const void* p) {
    uint32_t a;
    asm("{ .reg .u64 t; cvta.to.shared.u64 t, %1; cvt.u32.u64 %0, t; }" : "=r"(a) : "l"(p));
    return a;
}
__device__ __forceinline__ void ldmx4(uint32_t* r, uint32_t addr) {
    asm volatile("ldmatrix.sync.aligned.m8n8.x4.shared.b16 {%0,%1,%2,%3}, [%4];"
                 : "=r"(r[0]), "=r"(r[1]), "=r"(r[2]), "=r"(r[3]) : "r"(addr));
}
__device__ __forceinline__ void mma16816(float* d, const uint32_t* a, const uint32_t* b) {
    asm volatile(
        "mma.sync.aligned.m16n8k16.row.col.f32.bf16.bf16.f32 "
        "{%0,%1,%2,%3}, {%4,%5,%6,%7}, {%8,%9}, {%0,%1,%2,%3};"
        : "+f"(d[0]), "+f"(d[1]), "+f"(d[2]), "+f"(d[3])
        : "r"(a[0]), "r"(a[1]), "r"(a[2]), "r"(a[3]), "r"(b[0]), "r"(b[1]));
}
__device__ __forceinline__ void cp16(uint32_t dst, const void* src) {
    asm volatile("cp.async.cg.shared.global [%0], [%1], 16;" :: "r"(dst), "l"(src));
}
#define CP_COMMIT() asm volatile("cp.async.commit_group;" ::: "memory")
#define CP_WAIT(n)  asm volatile("cp.async.wait_group %0;" :: "n"(n) : "memory")

__device__ __forceinline__ uint32_t cvt2bf(float hi, float lo) {
    uint32_t r;
    asm("cvt.rn.bf16x2.f32 %0, %1, %2;" : "=r"(r) : "f"(hi), "f"(lo));
    return r;
}
__device__ __forceinline__ void sts64(uint32_t a, uint32_t x, uint32_t y) {
    asm volatile("st.shared.v2.b32 [%0], {%1,%2};" :: "r"(a), "r"(x), "r"(y) : "memory");
}

// ---------------------------------------------------------------------------
// K1: h = x @ W
// ---------------------------------------------------------------------------
__global__ __launch_bounds__(256) void k1_xw(const float* __restrict__ x,
                                             const float* __restrict__ W) {
    __shared__ float xs[64][33];
    __shared__ float Ws[32][128];
    const int tid = threadIdx.x;
    const int row0 = blockIdx.x * 64;
    const int ig = tid >> 4, og = tid & 15;
    const int iBase = ig * 4, oBase = og * 8;
    float acc[4][8];
#pragma unroll
    for (int a = 0; a < 4; a++)
#pragma unroll
        for (int c = 0; c < 8; c++) acc[a][c] = 0.f;

    const int seg = tid & 7, r = tid >> 3;
    for (int k0 = 0; k0 < 128; k0 += 32) {
#pragma unroll
        for (int p = 0; p < 2; p++) {
            int rr = r + p * 32;
            float4 v = *(const float4*)&x[(size_t)(row0 + rr) * 128 + k0 + seg * 4];
            xs[rr][seg * 4 + 0] = v.x; xs[rr][seg * 4 + 1] = v.y;
            xs[rr][seg * 4 + 2] = v.z; xs[rr][seg * 4 + 3] = v.w;
        }
        for (int idx = tid; idx < 32 * 128 / 4; idx += 256)
            *(float4*)(&Ws[0][0] + idx * 4) = *(const float4*)&W[(size_t)k0 * 128 + idx * 4];
        __syncthreads();
#pragma unroll 8
        for (int kk = 0; kk < 32; kk++) {
            float a0 = xs[iBase + 0][kk], a1 = xs[iBase + 1][kk];
            float a2 = xs[iBase + 2][kk], a3 = xs[iBase + 3][kk];
            float bv[8];
            *(float4*)&bv[0] = *(const float4*)&Ws[kk][oBase];
            *(float4*)&bv[4] = *(const float4*)&Ws[kk][oBase + 4];
#pragma unroll
            for (int c = 0; c < 8; c++) {
                acc[0][c] += a0 * bv[c];
                acc[1][c] += a1 * bv[c];
                acc[2][c] += a2 * bv[c];
                acc[3][c] += a3 * bv[c];
            }
        }
        __syncthreads();
    }
#pragma unroll
    for (int a = 0; a < 4; a++) {
        float* dst = &g_h[(size_t)(row0 + iBase + a) * 128 + oBase];
        *(float4*)&dst[0] = make_float4(acc[a][0], acc[a][1], acc[a][2], acc[a][3]);
        *(float4*)&dst[4] = make_float4(acc[a][4], acc[a][5], acc[a][6], acc[a][7]);
    }
}

// ---------------------------------------------------------------------------
// K1b: transpose h -> [b][o][j], split into bf16 hi/lo
// ---------------------------------------------------------------------------
__global__ __launch_bounds__(256) void k1b_split() {
    __shared__ float t[32][33];
    const int b = blockIdx.z;
    const int j0 = blockIdx.x * 32, o0 = blockIdx.y * 32;
    const int tx = threadIdx.x, ty = threadIdx.y;  // 32 x 8
#pragma unroll
    for (int r = 0; r < 32; r += 8)
        t[ty + r][tx] = g_h[((size_t)b * 2048 + j0 + ty + r) * 128 + o0 + tx];
    __syncthreads();
#pragma unroll
    for (int r = 0; r < 32; r += 8) {
        float v = t[tx][ty + r];
        __nv_bfloat16 h1 = __float2bfloat16_rn(v);
        float res = v - __bfloat162float(h1);
        size_t idx = ((size_t)b * 128 + o0 + ty + r) * 2048 + j0 + tx;
        g_hT1[idx] = h1;
        g_hT2[idx] = __float2bfloat16_rn(res);
    }
}

// ---------------------------------------------------------------------------
// K2: s_src / s_dst
// ---------------------------------------------------------------------------
__global__ __launch_bounds__(256) void k2_s(const float* __restrict__ a) {
    const int warp = threadIdx.x >> 5, lane = threadIdx.x & 31;
    const int row = blockIdx.x * 8 + warp;
    const float* h = &g_h[(size_t)row * 128];
    float s1 = 0.f, s2 = 0.f;
#pragma unroll
    for (int t = 0; t < 4; t++) {
        float hv = h[lane + 32 * t];
        s1 += hv * a[lane + 32 * t];
        s2 += hv * a[128 + lane + 32 * t];
    }
#pragma unroll
    for (int off = 16; off > 0; off >>= 1) {
        s1 += __shfl_xor_sync(0xffffffffu, s1, off);
        s2 += __shfl_xor_sync(0xffffffffu, s2, off);
    }
    if (lane == 0) { g_ssrc[row] = s1; g_sdst[row] = s2; }
}

// ---------------------------------------------------------------------------
// K3: rank sort of s_dst per batch — 8 threads per element, shfl-reduced
// ---------------------------------------------------------------------------
__global__ __launch_bounds__(1024) void k3_sort() {
    __shared__ float s[2048];
    const int b = blockIdx.y;
    const int tid = threadIdx.x;  // 1024
    for (int idx = tid; idx < 2048; idx += 1024) s[idx] = g_sdst[b * 2048 + idx];
    __syncthreads();
    const int jl = tid >> 3;                 // 0..127
    const int j = blockIdx.x * 128 + jl;
    const int chunk = tid & 7;
    const float my = s[j];
    int rank = 0;
    const int q0 = chunk * 256;
#pragma unroll 8
    for (int q = q0; q < q0 + 256; q++) {
        float o = s[q];
        rank += (o < my) || (o == my && q < j);
    }
#pragma unroll
    for (int off = 4; off > 0; off >>= 1)
        rank += __shfl_xor_sync(0xffffffffu, rank, off);
    if (chunk == 0) {
        const int base = b * 2048;
        g_v[base + rank]    = my;
        g_perm[base + rank] = j;
        g_w1[base + rank]   = expf(my);
        g_w02[base + rank]  = expf(SLOPE * my);
    }
}

// ---------------------------------------------------------------------------
// K4: fp32 chunked scans for numerator tables (grid (4,8), 1024 thr)
// ---------------------------------------------------------------------------
__global__ __launch_bounds__(1024) void k4_scanE() {
    __shared__ float cs1[32][33], cs02[32][33];
    __shared__ float off1A[32][32], off02A[32][32];
    __shared__ float tot1s[32];
    const int b = blockIdx.y;
    const int ol = threadIdx.x & 31;
    const int o = blockIdx.x * 32 + ol;
    const int c = threadIdx.x >> 5;
    const int base = b * 2048;
    const int r0 = c * 64;

    float a1 = 0.f, a02 = 0.f;
    for (int r = r0; r < r0 + 64; r++) {
        int j = g_perm[base + r];
        float hv = g_h[((size_t)(base + j)) * 128 + o];
        a1  += g_w1[base + r]  * hv;
        a02 += g_w02[base + r] * hv;
    }
    cs1[c][ol] = a1; cs02[c][ol] = a02;
    __syncthreads();
    if (c == 0) {
        float r1 = 0.f, r2 = 0.f;
        for (int q = 0; q < 32; q++) {
            off1A[q][ol] = r1;  r1 += cs1[q][ol];
            off02A[q][ol] = r2; r2 += cs02[q][ol];
        }
        tot1s[ol] = r1;
    }
    __syncthreads();
    float run1 = off1A[c][ol], run02 = off02A[c][ol];
    const float tot1 = tot1s[ol];
    const size_t tbase = ((size_t)b * 2049) * 128 + o;
    for (int r = r0; r < r0 + 64; r++) {
        int j = g_perm[base + r];
        float hv = g_h[((size_t)(base + j)) * 128 + o];
        g_suf1[tbase + (size_t)r * 128]  = tot1 - run1;
        run1 += g_w1[base + r] * hv;
        g_pre02[tbase + (size_t)r * 128] = run02;
        run02 += g_w02[base + r] * hv;
    }
    if (c == 31) {
        g_suf1[tbase + (size_t)2048 * 128]  = 0.f;
        g_pre02[tbase + (size_t)2048 * 128] = run02;
    }
}

// K4b: denominators (tiny, fp64)
__global__ __launch_bounds__(32) void k4b_scanD() {
    __shared__ double cs1[16], cs02[16], off1[16], off02[16], tot[2];
    const int b = blockIdx.x;
    const int c = threadIdx.x;
    const int base = b * 2048;
    if (c < 16) {
        double a1 = 0.0, a02 = 0.0;
        for (int r = c * 128; r < c * 128 + 128; r++) {
            a1 += (double)g_w1[base + r]; a02 += (double)g_w02[base + r];
        }
        cs1[c] = a1; cs02[c] = a02;
    }
    __syncthreads();
    if (c == 0) {
        double r1 = 0.0, r2 = 0.0;
        for (int q = 0; q < 16; q++) {
            off1[q] = r1; r1 += cs1[q];
            off02[q] = r2; r2 += cs02[q];
        }
        tot[0] = r1; tot[1] = r2;
    }
    __syncthreads();
    if (c < 16) {
        double run1 = off1[c], run02 = off02[c], t1 = tot[0];
        const size_t tb = (size_t)b * 2049;
        for (int r = c * 128; r < c * 128 + 128; r++) {
            g_sufD1[tb + r] = (float)(t1 - run1);
            run1 += (double)g_w1[base + r];
            g_preD02[tb + r] = (float)run02;
            run02 += (double)g_w02[base + r];
        }
        if (c == 15) { g_sufD1[tb + 2048] = 0.f; g_preD02[tb + 2048] = (float)run02; }
    }
}

// ---------------------------------------------------------------------------
// K5: mma.sync bf16 3-term split GEMM (adj@h) + attention epilogue + lrelu
// CTA tile 128(i) x 128(o), K=2048 in 32 chunks of 64. 8 warps = 2(i) x 4(o).
// 3-stage pipeline: cp.async (B) with wait_group 1 => each B load gets a full
// chunk of latency slack; A path = LDG (1 chunk ahead) -> register split -> STS.
// ---------------------------------------------------------------------------
#define STG_BYTES 73728u           // 4 tiles x 128 x 144B
#define OFF_AHI 0u
#define OFF_ALO 18432u
#define OFF_BHI 36864u
#define OFF_BLO 55296u
#define N_STAGE 3
#define K5_SMEM (N_STAGE * STG_BYTES)

__global__ __launch_bounds__(256) void k5_main(const float* __restrict__ adj,
                                               float* __restrict__ out) {
    extern __shared__ __align__(128) char dsm[];
    __shared__ int kS[128];
    __shared__ float e1S[128], e02S[128], dinvS[128];
    const uint32_t sb = smem_u32(dsm);
    const int tid = threadIdx.x;
    const int b = blockIdx.y;
    const int i0 = blockIdx.x * 128;

    // --- binary-search setup (uses dynamic smem as temp before tiles) ---
    {
        float* vS = (float*)dsm;
        for (int idx = tid; idx < 2048; idx += 256) vS[idx] = g_v[b * 2048 + idx];
        __syncthreads();
        if (tid < 128) {
            float si = g_ssrc[b * 2048 + i0 + tid];
            float target = -si;
            int lo = 0, hi = 2048;
            while (lo < hi) { int mid = (lo + hi) >> 1; if (vS[mid] < target) lo = mid + 1; else hi = mid; }
            float e1 = expf(si), e02 = expf(SLOPE * si);
            float Dv = e1 * g_sufD1[(size_t)b * 2049 + lo] + e02 * g_preD02[(size_t)b * 2049 + lo];
            kS[tid] = lo; e1S[tid] = e1; e02S[tid] = e02; dinvS[tid] = 1.0f / Dv;
        }
        __syncthreads();
    }

    // loader mapping: row = tid>>1 (0..127), half = tid&1 (32-col subchunk)
    const int row = tid >> 1, half = tid & 1;
    const float* aRow = adj + ((size_t)(b * 2048 + i0 + row)) * 2048 + half * 32;
    const __nv_bfloat16* b1Row = g_hT1 + ((size_t)(b * 128 + row)) * 2048 + half * 32;
    const __nv_bfloat16* b2Row = g_hT2 + ((size_t)(b * 128 + row)) * 2048 + half * 32;
    const uint32_t stsBase = (uint32_t)row * 144 + (uint32_t)half * 64;

    // compute mapping: warp -> (wi in {0,1}, wo in {0..3})
    const int warp = tid >> 5, lane = tid & 31;
    const int wi = warp & 1, wo = warp >> 1;
    const int obase = wo * 32;
    const uint32_t aLane = (uint32_t)(wi * 64 + (lane & 15)) * 144 + ((lane >> 4) << 4);
    const uint32_t bLane = (uint32_t)(obase + (lane & 7) + ((lane & 16) >> 1)) * 144 + ((lane & 8) << 1);

    float acc[4][4][4];
#pragma unroll
    for (int mf = 0; mf < 4; mf++)
#pragma unroll
        for (int nf = 0; nf < 4; nf++)
#pragma unroll
            for (int e = 0; e < 4; e++) acc[mf][nf][e] = 0.f;

    // ---- A convert+store helper as lambda-ish macro via inline code ----
    // prologue: fill stages 0 and 1 with chunks 0 and 1
#pragma unroll
    for (int pc = 0; pc < 2; pc++) {
        const uint32_t sOff = sb + pc * STG_BYTES;
        const int j0 = pc * 64;
#pragma unroll
        for (int p = 0; p < 4; p++) {
            cp16(sOff + OFF_BHI + stsBase + p * 16, b1Row + j0 + p * 8);
            cp16(sOff + OFF_BLO + stsBase + p * 16, b2Row + j0 + p * 8);
        }
        CP_COMMIT();
#pragma unroll
        for (int p = 0; p < 8; p++) {
            float4 u = *(const float4*)(aRow + j0 + p * 4);
            uint32_t hi = cvt2bf(u.y, u.x);
            uint32_t hj = cvt2bf(u.w, u.z);
            float l0 = u.x - __uint_as_float(hi << 16);
            float l1 = u.y - __uint_as_float(hi & 0xffff0000u);
            float l2 = u.z - __uint_as_float(hj << 16);
            float l3 = u.w - __uint_as_float(hj & 0xffff0000u);
            sts64(sOff + OFF_AHI + stsBase + p * 8, hi, hj);
            sts64(sOff + OFF_ALO + stsBase + p * 8, cvt2bf(l1, l0), cvt2bf(l3, l2));
        }
    }
    CP_WAIT(1);           // B(0) complete; B(1) may still fly
    __syncthreads();

    for (int c = 0; c < 32; c++) {
        const uint32_t sCur = sb + (uint32_t)(c % N_STAGE) * STG_BYTES;
        const uint32_t sNxt = sb + (uint32_t)((c + 2) % N_STAGE) * STG_BYTES;
        const int j2 = (c + 2) * 64;
        float4 fA[8];
        if (c < 30) {
#pragma unroll
            for (int p = 0; p < 4; p++) {
                cp16(sNxt + OFF_BHI + stsBase + p * 16, b1Row + j2 + p * 8);
                cp16(sNxt + OFF_BLO + stsBase + p * 16, b2Row + j2 + p * 8);
            }
            CP_COMMIT();
#pragma unroll
            for (int p = 0; p < 8; p++) fA[p] = *(const float4*)(aRow + j2 + p * 4);
        }
        // ---- compute current chunk: 4 k16 steps ----
#pragma unroll
        for (int kk = 0; kk < 4; kk++) {
            uint32_t aH[4][4], aL[4][4], bH[8], bL[8];
            const uint32_t aAddr = sCur + aLane + kk * 32;
            const uint32_t bAddr = sCur + bLane + kk * 32;
#pragma unroll
            for (int mf = 0; mf < 4; mf++) {
                ldmx4(aH[mf], aAddr + OFF_AHI + mf * (16 * 144));
                ldmx4(aL[mf], aAddr + OFF_ALO + mf * (16 * 144));
            }
            ldmx4(&bH[0], bAddr + OFF_BHI);
            ldmx4(&bH[4], bAddr + OFF_BHI + 16 * 144);
            ldmx4(&bL[0], bAddr + OFF_BLO);
            ldmx4(&bL[4], bAddr + OFF_BLO + 16 * 144);
#pragma unroll
            for (int mf = 0; mf < 4; mf++)
#pragma unroll
                for (int nf = 0; nf < 4; nf++) {
                    mma16816(acc[mf][nf], aH[mf], &bH[nf * 2]);
                    mma16816(acc[mf][nf], aH[mf], &bL[nf * 2]);
                    mma16816(acc[mf][nf], aL[mf], &bH[nf * 2]);
                }
        }
        if (c < 30) {
#pragma unroll
            for (int p = 0; p < 8; p++) {
                float4 u = fA[p];
                uint32_t hi = cvt2bf(u.y, u.x);
                uint32_t hj = cvt2bf(u.w, u.z);
                float l0 = u.x - __uint_as_float(hi << 16);
                float l1 = u.y - __uint_as_float(hi & 0xffff0000u);
                float l2 = u.z - __uint_as_float(hj << 16);
                float l3 = u.w - __uint_as_float(hj & 0xffff0000u);
                sts64(sNxt + OFF_AHI + stsBase + p * 8, hi, hj);
                sts64(sNxt + OFF_ALO + stsBase + p * 8, cvt2bf(l1, l0), cvt2bf(l3, l2));
            }
            CP_WAIT(1);   // B(c+1) complete; B(c+2) may still fly
        } else {
            CP_WAIT(0);   // tail: drain everything (B31 needed next iter)
        }
        __syncthreads();
    }

    // ---- epilogue: attention lookup + lrelu + store ----
#pragma unroll
    for (int mf = 0; mf < 4; mf++) {
        const int rl0 = wi * 64 + mf * 16 + (lane >> 2);
#pragma unroll
        for (int hh = 0; hh < 2; hh++) {
            const int rl = rl0 + hh * 8;
            const int k = kS[rl];
            const float e1 = e1S[rl], e02 = e02S[rl], dinv = dinvS[rl];
            const float* suf = &g_suf1[((size_t)(b * 2049 + k)) * 128];
            const float* pre = &g_pre02[((size_t)(b * 2049 + k)) * 128];
            float* dst = &out[((size_t)(b * 2048 + i0 + rl)) * 128];
#pragma unroll
            for (int nf = 0; nf < 4; nf++) {
                const int o = obase + nf * 8 + (lane & 3) * 2;
                float2 sf = *(const float2*)&suf[o];
                float2 pf = *(const float2*)&pre[o];
                float v0 = acc[mf][nf][hh * 2 + 0] + (e1 * sf.x + e02 * pf.x) * dinv;
                float v1 = acc[mf][nf][hh * 2 + 1] + (e1 * sf.y + e02 * pf.y) * dinv;
                float2 r;
                r.x = v0 >= 0.f ? v0 : SLOPE * v0;
                r.y = v1 >= 0.f ? v1 : SLOPE * v1;
                *(float2*)&dst[o] = r;
            }
        }
    }
}

// ---------------------------------------------------------------------------
extern "C" void kernel_launch(void* const* d_in, const int* in_sizes, int n_in,
                              void* d_out, int out_size) {
    (void)in_sizes; (void)n_in; (void)out_size;
    const float* x   = (const float*)d_in[0];
    const float* adj = (const float*)d_in[1];
    const float* W   = (const float*)d_in[2];
    const float* a   = (const float*)d_in[3];
    float* out = (float*)d_out;

    cudaFuncSetAttribute(k5_main, cudaFuncAttributeMaxDynamicSharedMemorySize, K5_SMEM);

    k1_xw<<<256, 256>>>(x, W);
    k1b_split<<<dim3(64, 4, 8), dim3(32, 8)>>>();
    k2_s<<<2048, 256>>>(a);
    k3_sort<<<dim3(16, 8), 1024>>>();
    k4_scanE<<<dim3(4, 8), 1024>>>();
    k4b_scanD<<<8, 32>>>();
    k5_main<<<dim3(16, 8), 256, K5_SMEM>>>(adj, out);
}

// round 7
// speedup vs baseline: 1.2005x; 1.2005x over previous
#include <cuda_runtime.h>
#include <cuda_bf16.h>
#include <math.h>
#include <stdint.h>

#define SLOPE 0.2f

// Shapes fixed: B=8, N=2048, D=128.
__device__ float g_h[8 * 2048 * 128];           // h = x @ W (fp32)
__device__ __nv_bfloat16 g_hT1[8 * 128 * 2048]; // hi bf16 of h, transposed [b][o][j]
__device__ __nv_bfloat16 g_hT2[8 * 128 * 2048]; // lo bf16 residual
__device__ float g_ssrc[8 * 2048];
__device__ float g_sdst[8 * 2048];
__device__ float g_v[8 * 2048];
__device__ int   g_perm[8 * 2048];
__device__ float g_w1[8 * 2048];
__device__ float g_w02[8 * 2048];
__device__ float g_suf1[8 * 2049 * 128];
__device__ float g_pre02[8 * 2049 * 128];
__device__ float g_sufD1[8 * 2049];
__device__ float g_preD02[8 * 2049];

// ---------------------------------------------------------------------------
// helpers (all sm_80-era: ldmatrix / cp.async / mma.sync — no 'a'-gated instrs)
// ---------------------------------------------------------------------------
__device__ __forceinline__ uint32_t smem_u32(const void* p) {
    uint32_t a;
    asm("{ .reg .u64 t; cvta.to.shared.u64 t, %1; cvt.u32.u64 %0, t; }" : "=r"(a) : "l"(p));
    return a;
}
__device__ __forceinline__ void ldmx4(uint32_t* r, uint32_t addr) {
    asm volatile("ldmatrix.sync.aligned.m8n8.x4.shared.b16 {%0,%1,%2,%3}, [%4];"
                 : "=r"(r[0]), "=r"(r[1]), "=r"(r[2]), "=r"(r[3]) : "r"(addr));
}
__device__ __forceinline__ void mma16816(float* d, const uint32_t* a, const uint32_t* b) {
    asm volatile(
        "mma.sync.aligned.m16n8k16.row.col.f32.bf16.bf16.f32 "
        "{%0,%1,%2,%3}, {%4,%5,%6,%7}, {%8,%9}, {%0,%1,%2,%3};"
        : "+f"(d[0]), "+f"(d[1]), "+f"(d[2]), "+f"(d[3])
        : "r"(a[0]), "r"(a[1]), "r"(a[2]), "r"(a[3]), "r"(b[0]), "r"(b[1]));
}
__device__ __forceinline__ void cp16(uint32_t dst, const void* src) {
    asm volatile("cp.async.cg.shared.global [%0], [%1], 16;" :: "r"(dst), "l"(src));
}
#define CP_COMMIT() asm volatile("cp.async.commit_group;" ::: "memory")
#define CP_WAIT0()  asm volatile("cp.async.wait_group 0;" ::: "memory")

__device__ __forceinline__ uint32_t cvt2bf(float hi, float lo) {
    uint32_t r;
    asm("cvt.rn.bf16x2.f32 %0, %1, %2;" : "=r"(r) : "f"(hi), "f"(lo));
    return r;
}
__device__ __forceinline__ void sts64(uint32_t a, uint32_t x, uint32_t y) {
    asm volatile("st.shared.v2.b32 [%0], {%1,%2};" :: "r"(a), "r"(x), "r"(y) : "memory");
}

// ---------------------------------------------------------------------------
// K1: h = x @ W
// ---------------------------------------------------------------------------
__global__ __launch_bounds__(256) void k1_xw(const float* __restrict__ x,
                                             const float* __restrict__ W) {
    __shared__ float xs[64][33];
    __shared__ float Ws[32][128];
    const int tid = threadIdx.x;
    const int row0 = blockIdx.x * 64;
    const int ig = tid >> 4, og = tid & 15;
    const int iBase = ig * 4, oBase = og * 8;
    float acc[4][8];
#pragma unroll
    for (int a = 0; a < 4; a++)
#pragma unroll
        for (int c = 0; c < 8; c++) acc[a][c] = 0.f;

    const int seg = tid & 7, r = tid >> 3;
    for (int k0 = 0; k0 < 128; k0 += 32) {
#pragma unroll
        for (int p = 0; p < 2; p++) {
            int rr = r + p * 32;
            float4 v = *(const float4*)&x[(size_t)(row0 + rr) * 128 + k0 + seg * 4];
            xs[rr][seg * 4 + 0] = v.x; xs[rr][seg * 4 + 1] = v.y;
            xs[rr][seg * 4 + 2] = v.z; xs[rr][seg * 4 + 3] = v.w;
        }
        for (int idx = tid; idx < 32 * 128 / 4; idx += 256)
            *(float4*)(&Ws[0][0] + idx * 4) = *(const float4*)&W[(size_t)k0 * 128 + idx * 4];
        __syncthreads();
#pragma unroll 8
        for (int kk = 0; kk < 32; kk++) {
            float a0 = xs[iBase + 0][kk], a1 = xs[iBase + 1][kk];
            float a2 = xs[iBase + 2][kk], a3 = xs[iBase + 3][kk];
            float bv[8];
            *(float4*)&bv[0] = *(const float4*)&Ws[kk][oBase];
            *(float4*)&bv[4] = *(const float4*)&Ws[kk][oBase + 4];
#pragma unroll
            for (int c = 0; c < 8; c++) {
                acc[0][c] += a0 * bv[c];
                acc[1][c] += a1 * bv[c];
                acc[2][c] += a2 * bv[c];
                acc[3][c] += a3 * bv[c];
            }
        }
        __syncthreads();
    }
#pragma unroll
    for (int a = 0; a < 4; a++) {
        float* dst = &g_h[(size_t)(row0 + iBase + a) * 128 + oBase];
        *(float4*)&dst[0] = make_float4(acc[a][0], acc[a][1], acc[a][2], acc[a][3]);
        *(float4*)&dst[4] = make_float4(acc[a][4], acc[a][5], acc[a][6], acc[a][7]);
    }
}

// ---------------------------------------------------------------------------
// K1b: transpose h -> [b][o][j], split into bf16 hi/lo
// ---------------------------------------------------------------------------
__global__ __launch_bounds__(256) void k1b_split() {
    __shared__ float t[32][33];
    const int b = blockIdx.z;
    const int j0 = blockIdx.x * 32, o0 = blockIdx.y * 32;
    const int tx = threadIdx.x, ty = threadIdx.y;  // 32 x 8
#pragma unroll
    for (int r = 0; r < 32; r += 8)
        t[ty + r][tx] = g_h[((size_t)b * 2048 + j0 + ty + r) * 128 + o0 + tx];
    __syncthreads();
#pragma unroll
    for (int r = 0; r < 32; r += 8) {
        float v = t[tx][ty + r];
        __nv_bfloat16 h1 = __float2bfloat16_rn(v);
        float res = v - __bfloat162float(h1);
        size_t idx = ((size_t)b * 128 + o0 + ty + r) * 2048 + j0 + tx;
        g_hT1[idx] = h1;
        g_hT2[idx] = __float2bfloat16_rn(res);
    }
}

// ---------------------------------------------------------------------------
// K2: s_src / s_dst
// ---------------------------------------------------------------------------
__global__ __launch_bounds__(256) void k2_s(const float* __restrict__ a) {
    const int warp = threadIdx.x >> 5, lane = threadIdx.x & 31;
    const int row = blockIdx.x * 8 + warp;
    const float* h = &g_h[(size_t)row * 128];
    float s1 = 0.f, s2 = 0.f;
#pragma unroll
    for (int t = 0; t < 4; t++) {
        float hv = h[lane + 32 * t];
        s1 += hv * a[lane + 32 * t];
        s2 += hv * a[128 + lane + 32 * t];
    }
#pragma unroll
    for (int off = 16; off > 0; off >>= 1) {
        s1 += __shfl_xor_sync(0xffffffffu, s1, off);
        s2 += __shfl_xor_sync(0xffffffffu, s2, off);
    }
    if (lane == 0) { g_ssrc[row] = s1; g_sdst[row] = s2; }
}

// ---------------------------------------------------------------------------
// K3: rank sort — float4 LDS (1 load / 4 compares), 2 threads per element
// grid (16, 8), 256 threads: tid&127 -> local j, tid>>7 -> q-half
// ---------------------------------------------------------------------------
__global__ __launch_bounds__(256) void k3_sort() {
    __shared__ float s[2048];
    __shared__ int partial[256];
    const int b = blockIdx.y;
    const int tid = threadIdx.x;  // 256
    for (int idx = tid; idx < 2048; idx += 256) s[idx] = g_sdst[b * 2048 + idx];
    __syncthreads();
    const int jl = tid & 127;
    const int half = tid >> 7;
    const int j = blockIdx.x * 128 + jl;
    const float my = s[j];
    int rank = 0;
    const int q0 = half * 1024;
#pragma unroll 4
    for (int q = q0; q < q0 + 1024; q += 4) {
        float4 v = *(const float4*)&s[q];
        rank += (v.x < my) || (v.x == my && (q + 0) < j);
        rank += (v.y < my) || (v.y == my && (q + 1) < j);
        rank += (v.z < my) || (v.z == my && (q + 2) < j);
        rank += (v.w < my) || (v.w == my && (q + 3) < j);
    }
    partial[tid] = rank;
    __syncthreads();
    if (tid < 128) {
        const int r = partial[tid] + partial[tid + 128];
        const int base = b * 2048;
        g_v[base + r]    = my;
        g_perm[base + r] = j;
        g_w1[base + r]   = expf(my);
        g_w02[base + r]  = expf(SLOPE * my);
    }
}

// ---------------------------------------------------------------------------
// K4: fp32 chunked scans for numerator tables (grid (4,8), 1024 thr)
// ---------------------------------------------------------------------------
__global__ __launch_bounds__(1024) void k4_scanE() {
    __shared__ float cs1[32][33], cs02[32][33];
    __shared__ float off1A[32][32], off02A[32][32];
    __shared__ float tot1s[32];
    const int b = blockIdx.y;
    const int ol = threadIdx.x & 31;
    const int o = blockIdx.x * 32 + ol;
    const int c = threadIdx.x >> 5;
    const int base = b * 2048;
    const int r0 = c * 64;

    float a1 = 0.f, a02 = 0.f;
    for (int r = r0; r < r0 + 64; r++) {
        int j = g_perm[base + r];
        float hv = g_h[((size_t)(base + j)) * 128 + o];
        a1  += g_w1[base + r]  * hv;
        a02 += g_w02[base + r] * hv;
    }
    cs1[c][ol] = a1; cs02[c][ol] = a02;
    __syncthreads();
    if (c == 0) {
        float r1 = 0.f, r2 = 0.f;
        for (int q = 0; q < 32; q++) {
            off1A[q][ol] = r1;  r1 += cs1[q][ol];
            off02A[q][ol] = r2; r2 += cs02[q][ol];
        }
        tot1s[ol] = r1;
    }
    __syncthreads();
    float run1 = off1A[c][ol], run02 = off02A[c][ol];
    const float tot1 = tot1s[ol];
    const size_t tbase = ((size_t)b * 2049) * 128 + o;
    for (int r = r0; r < r0 + 64; r++) {
        int j = g_perm[base + r];
        float hv = g_h[((size_t)(base + j)) * 128 + o];
        g_suf1[tbase + (size_t)r * 128]  = tot1 - run1;
        run1 += g_w1[base + r] * hv;
        g_pre02[tbase + (size_t)r * 128] = run02;
        run02 += g_w02[base + r] * hv;
    }
    if (c == 31) {
        g_suf1[tbase + (size_t)2048 * 128]  = 0.f;
        g_pre02[tbase + (size_t)2048 * 128] = run02;
    }
}

// K4b: denominators (tiny, fp64)
__global__ __launch_bounds__(32) void k4b_scanD() {
    __shared__ double cs1[16], cs02[16], off1[16], off02[16], tot[2];
    const int b = blockIdx.x;
    const int c = threadIdx.x;
    const int base = b * 2048;
    if (c < 16) {
        double a1 = 0.0, a02 = 0.0;
        for (int r = c * 128; r < c * 128 + 128; r++) {
            a1 += (double)g_w1[base + r]; a02 += (double)g_w02[base + r];
        }
        cs1[c] = a1; cs02[c] = a02;
    }
    __syncthreads();
    if (c == 0) {
        double r1 = 0.0, r2 = 0.0;
        for (int q = 0; q < 16; q++) {
            off1[q] = r1; r1 += cs1[q];
            off02[q] = r2; r2 += cs02[q];
        }
        tot[0] = r1; tot[1] = r2;
    }
    __syncthreads();
    if (c < 16) {
        double run1 = off1[c], run02 = off02[c], t1 = tot[0];
        const size_t tb = (size_t)b * 2049;
        for (int r = c * 128; r < c * 128 + 128; r++) {
            g_sufD1[tb + r] = (float)(t1 - run1);
            run1 += (double)g_w1[base + r];
            g_preD02[tb + r] = (float)run02;
            run02 += (double)g_w02[base + r];
        }
        if (c == 15) { g_sufD1[tb + 2048] = 0.f; g_preD02[tb + 2048] = (float)run02; }
    }
}

// ---------------------------------------------------------------------------
// K5: mma.sync bf16 3-term split GEMM (adj@h) + attention epilogue + lrelu
// (exact R4 2-stage pipeline — reverted from the 3-stage regression)
// ---------------------------------------------------------------------------
#define STG_BYTES 73728u           // 4 tiles x 128 x 144B
#define OFF_AHI 0u
#define OFF_ALO 18432u
#define OFF_BHI 36864u
#define OFF_BLO 55296u
#define K5_SMEM (2 * STG_BYTES)

__global__ __launch_bounds__(256) void k5_main(const float* __restrict__ adj,
                                               float* __restrict__ out) {
    extern __shared__ __align__(128) char dsm[];
    __shared__ int kS[128];
    __shared__ float e1S[128], e02S[128], dinvS[128];
    const uint32_t sb = smem_u32(dsm);
    const int tid = threadIdx.x;
    const int b = blockIdx.y;
    const int i0 = blockIdx.x * 128;

    // --- binary-search setup (uses dynamic smem as temp before tiles) ---
    {
        float* vS = (float*)dsm;
        for (int idx = tid; idx < 2048; idx += 256) vS[idx] = g_v[b * 2048 + idx];
        __syncthreads();
        if (tid < 128) {
            float si = g_ssrc[b * 2048 + i0 + tid];
            float target = -si;
            int lo = 0, hi = 2048;
            while (lo < hi) { int mid = (lo + hi) >> 1; if (vS[mid] < target) lo = mid + 1; else hi = mid; }
            float e1 = expf(si), e02 = expf(SLOPE * si);
            float Dv = e1 * g_sufD1[(size_t)b * 2049 + lo] + e02 * g_preD02[(size_t)b * 2049 + lo];
            kS[tid] = lo; e1S[tid] = e1; e02S[tid] = e02; dinvS[tid] = 1.0f / Dv;
        }
        __syncthreads();
    }

    // loader mapping: row = tid>>1 (0..127), half = tid&1 (32-col subchunk)
    const int row = tid >> 1, half = tid & 1;
    const float* aRow = adj + ((size_t)(b * 2048 + i0 + row)) * 2048 + half * 32;
    const __nv_bfloat16* b1Row = g_hT1 + ((size_t)(b * 128 + row)) * 2048 + half * 32;
    const __nv_bfloat16* b2Row = g_hT2 + ((size_t)(b * 128 + row)) * 2048 + half * 32;
    const uint32_t stsBase = (uint32_t)row * 144 + (uint32_t)half * 64;

    // compute mapping: warp -> (wi in {0,1}, wo in {0..3})
    const int warp = tid >> 5, lane = tid & 31;
    const int wi = warp & 1, wo = warp >> 1;
    const int obase = wo * 32;
    const uint32_t aLane = (uint32_t)(wi * 64 + (lane & 15)) * 144 + ((lane >> 4) << 4);
    const uint32_t bLane = (uint32_t)(obase + (lane & 7) + ((lane & 16) >> 1)) * 144 + ((lane & 8) << 1);

    float acc[4][4][4];
#pragma unroll
    for (int mf = 0; mf < 4; mf++)
#pragma unroll
        for (int nf = 0; nf < 4; nf++)
#pragma unroll
            for (int e = 0; e < 4; e++) acc[mf][nf][e] = 0.f;

    // ---- prologue: stage 0 <- chunk 0 ----
    {
#pragma unroll
        for (int p = 0; p < 4; p++) {
            cp16(sb + OFF_BHI + stsBase + p * 16, b1Row + p * 8);
            cp16(sb + OFF_BLO + stsBase + p * 16, b2Row + p * 8);
        }
        CP_COMMIT();
#pragma unroll
        for (int p = 0; p < 8; p++) {
            float4 u = *(const float4*)(aRow + p * 4);
            uint32_t hi = cvt2bf(u.y, u.x);
            uint32_t hj = cvt2bf(u.w, u.z);
            float l0 = u.x - __uint_as_float(hi << 16);
            float l1 = u.y - __uint_as_float(hi & 0xffff0000u);
            float l2 = u.z - __uint_as_float(hj << 16);
            float l3 = u.w - __uint_as_float(hj & 0xffff0000u);
            sts64(sb + OFF_AHI + stsBase + p * 8, hi, hj);
            sts64(sb + OFF_ALO + stsBase + p * 8, cvt2bf(l1, l0), cvt2bf(l3, l2));
        }
        CP_WAIT0();
        __syncthreads();
    }

    for (int c = 0; c < 32; c++) {
        const uint32_t sCur = sb + (c & 1 ? STG_BYTES : 0u);
        const uint32_t sNxt = sb + (c & 1 ? 0u : STG_BYTES);
        const int j1 = (c + 1) * 64;
        float4 fA[8];
        if (c < 31) {
#pragma unroll
            for (int p = 0; p < 4; p++) {
                cp16(sNxt + OFF_BHI + stsBase + p * 16, b1Row + j1 + p * 8);
                cp16(sNxt + OFF_BLO + stsBase + p * 16, b2Row + j1 + p * 8);
            }
            CP_COMMIT();
#pragma unroll
            for (int p = 0; p < 8; p++) fA[p] = *(const float4*)(aRow + j1 + p * 4);
        }
        // ---- compute current chunk: 4 k16 steps ----
#pragma unroll
        for (int kk = 0; kk < 4; kk++) {
            uint32_t aH[4][4], aL[4][4], bH[8], bL[8];
            const uint32_t aAddr = sCur + aLane + kk * 32;
            const uint32_t bAddr = sCur + bLane + kk * 32;
#pragma unroll
            for (int mf = 0; mf < 4; mf++) {
                ldmx4(aH[mf], aAddr + OFF_AHI + mf * (16 * 144));
                ldmx4(aL[mf], aAddr + OFF_ALO + mf * (16 * 144));
            }
            ldmx4(&bH[0], bAddr + OFF_BHI);
            ldmx4(&bH[4], bAddr + OFF_BHI + 16 * 144);
            ldmx4(&bL[0], bAddr + OFF_BLO);
            ldmx4(&bL[4], bAddr + OFF_BLO + 16 * 144);
#pragma unroll
            for (int mf = 0; mf < 4; mf++)
#pragma unroll
                for (int nf = 0; nf < 4; nf++) {
                    mma16816(acc[mf][nf], aH[mf], &bH[nf * 2]);
                    mma16816(acc[mf][nf], aH[mf], &bL[nf * 2]);
                    mma16816(acc[mf][nf], aL[mf], &bH[nf * 2]);
                }
        }
        if (c < 31) {
#pragma unroll
            for (int p = 0; p < 8; p++) {
                float4 u = fA[p];
                uint32_t hi = cvt2bf(u.y, u.x);
                uint32_t hj = cvt2bf(u.w, u.z);
                float l0 = u.x - __uint_as_float(hi << 16);
                float l1 = u.y - __uint_as_float(hi & 0xffff0000u);
                float l2 = u.z - __uint_as_float(hj << 16);
                float l3 = u.w - __uint_as_float(hj & 0xffff0000u);
                sts64(sNxt + OFF_AHI + stsBase + p * 8, hi, hj);
                sts64(sNxt + OFF_ALO + stsBase + p * 8, cvt2bf(l1, l0), cvt2bf(l3, l2));
            }
        }
        CP_WAIT0();
        __syncthreads();
    }

    // ---- epilogue: attention lookup + lrelu + store ----
#pragma unroll
    for (int mf = 0; mf < 4; mf++) {
        const int rl0 = wi * 64 + mf * 16 + (lane >> 2);
#pragma unroll
        for (int hh = 0; hh < 2; hh++) {
            const int rl = rl0 + hh * 8;
            const int k = kS[rl];
            const float e1 = e1S[rl], e02 = e02S[rl], dinv = dinvS[rl];
            const float* suf = &g_suf1[((size_t)(b * 2049 + k)) * 128];
            const float* pre = &g_pre02[((size_t)(b * 2049 + k)) * 128];
            float* dst = &out[((size_t)(b * 2048 + i0 + rl)) * 128];
#pragma unroll
            for (int nf = 0; nf < 4; nf++) {
                const int o = obase + nf * 8 + (lane & 3) * 2;
                float2 sf = *(const float2*)&suf[o];
                float2 pf = *(const float2*)&pre[o];
                float v0 = acc[mf][nf][hh * 2 + 0] + (e1 * sf.x + e02 * pf.x) * dinv;
                float v1 = acc[mf][nf][hh * 2 + 1] + (e1 * sf.y + e02 * pf.y) * dinv;
                float2 r;
                r.x = v0 >= 0.f ? v0 : SLOPE * v0;
                r.y = v1 >= 0.f ? v1 : SLOPE * v1;
                *(float2*)&dst[o] = r;
            }
        }
    }
}

// ---------------------------------------------------------------------------
extern "C" void kernel_launch(void* const* d_in, const int* in_sizes, int n_in,
                              void* d_out, int out_size) {
    (void)in_sizes; (void)n_in; (void)out_size;
    const float* x   = (const float*)d_in[0];
    const float* adj = (const float*)d_in[1];
    const float* W   = (const float*)d_in[2];
    const float* a   = (const float*)d_in[3];
    float* out = (float*)d_out;

    cudaFuncSetAttribute(k5_main, cudaFuncAttributeMaxDynamicSharedMemorySize, K5_SMEM);

    k1_xw<<<256, 256>>>(x, W);
    k1b_split<<<dim3(64, 4, 8), dim3(32, 8)>>>();
    k2_s<<<2048, 256>>>(a);
    k3_sort<<<dim3(16, 8), 256>>>();
    k4_scanE<<<dim3(4, 8), 1024>>>();
    k4b_scanD<<<8, 32>>>();
    k5_main<<<dim3(16, 8), 256, K5_SMEM>>>(adj, out);
}

// round 8
// speedup vs baseline: 1.4412x; 1.2005x over previous
#include <cuda_runtime.h>
#include <cuda_fp16.h>
#include <math.h>
#include <stdint.h>

#define SLOPE 0.2f

// Shapes fixed: B=8, N=2048, D=128.
__device__ float g_h[8 * 2048 * 128];     // h = x @ W (fp32)
__device__ __half g_hT[8 * 128 * 2048];   // fp16 h, transposed [b][o][j]
__device__ float g_ssrc[8 * 2048];
__device__ float g_sdst[8 * 2048];
__device__ float g_v[8 * 2048];
__device__ int   g_perm[8 * 2048];
__device__ float g_w1[8 * 2048];
__device__ float g_w02[8 * 2048];
__device__ float g_suf1[8 * 2049 * 128];
__device__ float g_pre02[8 * 2049 * 128];
__device__ float g_sufD1[8 * 2049];
__device__ float g_preD02[8 * 2049];

// ---------------------------------------------------------------------------
// helpers
// ---------------------------------------------------------------------------
__device__ __forceinline__ uint32_t smem_u32(const void* p) {
    uint32_t a;
    asm("{ .reg .u64 t; cvta.to.shared.u64 t, %1; cvt.u32.u64 %0, t; }" : "=r"(a) : "l"(p));
    return a;
}
__device__ __forceinline__ void ldmx4(uint32_t* r, uint32_t addr) {
    asm volatile("ldmatrix.sync.aligned.m8n8.x4.shared.b16 {%0,%1,%2,%3}, [%4];"
                 : "=r"(r[0]), "=r"(r[1]), "=r"(r[2]), "=r"(r[3]) : "r"(addr));
}
__device__ __forceinline__ void mma16816(float* d, const uint32_t* a, const uint32_t* b) {
    asm volatile(
        "mma.sync.aligned.m16n8k16.row.col.f32.f16.f16.f32 "
        "{%0,%1,%2,%3}, {%4,%5,%6,%7}, {%8,%9}, {%0,%1,%2,%3};"
        : "+f"(d[0]), "+f"(d[1]), "+f"(d[2]), "+f"(d[3])
        : "r"(a[0]), "r"(a[1]), "r"(a[2]), "r"(a[3]), "r"(b[0]), "r"(b[1]));
}
__device__ __forceinline__ void cp16(uint32_t dst, const void* src) {
    asm volatile("cp.async.cg.shared.global [%0], [%1], 16;" :: "r"(dst), "l"(src));
}
#define CP_COMMIT() asm volatile("cp.async.commit_group;" ::: "memory")
#define CP_WAIT0()  asm volatile("cp.async.wait_group 0;" ::: "memory")

__device__ __forceinline__ uint32_t cvt2h(float hi, float lo) {
    uint32_t r;
    asm("cvt.rn.f16x2.f32 %0, %1, %2;" : "=r"(r) : "f"(hi), "f"(lo));
    return r;
}
__device__ __forceinline__ void sts128(uint32_t a, uint32_t x, uint32_t y, uint32_t z, uint32_t w) {
    asm volatile("st.shared.v4.b32 [%0], {%1,%2,%3,%4};" :: "r"(a), "r"(x), "r"(y), "r"(z), "r"(w) : "memory");
}

// ---------------------------------------------------------------------------
// K1: h = x @ W
// ---------------------------------------------------------------------------
__global__ __launch_bounds__(256) void k1_xw(const float* __restrict__ x,
                                             const float* __restrict__ W) {
    __shared__ float xs[64][33];
    __shared__ float Ws[32][128];
    const int tid = threadIdx.x;
    const int row0 = blockIdx.x * 64;
    const int ig = tid >> 4, og = tid & 15;
    const int iBase = ig * 4, oBase = og * 8;
    float acc[4][8];
#pragma unroll
    for (int a = 0; a < 4; a++)
#pragma unroll
        for (int c = 0; c < 8; c++) acc[a][c] = 0.f;

    const int seg = tid & 7, r = tid >> 3;
    for (int k0 = 0; k0 < 128; k0 += 32) {
#pragma unroll
        for (int p = 0; p < 2; p++) {
            int rr = r + p * 32;
            float4 v = *(const float4*)&x[(size_t)(row0 + rr) * 128 + k0 + seg * 4];
            xs[rr][seg * 4 + 0] = v.x; xs[rr][seg * 4 + 1] = v.y;
            xs[rr][seg * 4 + 2] = v.z; xs[rr][seg * 4 + 3] = v.w;
        }
        for (int idx = tid; idx < 32 * 128 / 4; idx += 256)
            *(float4*)(&Ws[0][0] + idx * 4) = *(const float4*)&W[(size_t)k0 * 128 + idx * 4];
        __syncthreads();
#pragma unroll 8
        for (int kk = 0; kk < 32; kk++) {
            float a0 = xs[iBase + 0][kk], a1 = xs[iBase + 1][kk];
            float a2 = xs[iBase + 2][kk], a3 = xs[iBase + 3][kk];
            float bv[8];
            *(float4*)&bv[0] = *(const float4*)&Ws[kk][oBase];
            *(float4*)&bv[4] = *(const float4*)&Ws[kk][oBase + 4];
#pragma unroll
            for (int c = 0; c < 8; c++) {
                acc[0][c] += a0 * bv[c];
                acc[1][c] += a1 * bv[c];
                acc[2][c] += a2 * bv[c];
                acc[3][c] += a3 * bv[c];
            }
        }
        __syncthreads();
    }
#pragma unroll
    for (int a = 0; a < 4; a++) {
        float* dst = &g_h[(size_t)(row0 + iBase + a) * 128 + oBase];
        *(float4*)&dst[0] = make_float4(acc[a][0], acc[a][1], acc[a][2], acc[a][3]);
        *(float4*)&dst[4] = make_float4(acc[a][4], acc[a][5], acc[a][6], acc[a][7]);
    }
}

// ---------------------------------------------------------------------------
// K1b: transpose h -> [b][o][j], convert to fp16
// ---------------------------------------------------------------------------
__global__ __launch_bounds__(256) void k1b_split() {
    __shared__ float t[32][33];
    const int b = blockIdx.z;
    const int j0 = blockIdx.x * 32, o0 = blockIdx.y * 32;
    const int tx = threadIdx.x, ty = threadIdx.y;  // 32 x 8
#pragma unroll
    for (int r = 0; r < 32; r += 8)
        t[ty + r][tx] = g_h[((size_t)b * 2048 + j0 + ty + r) * 128 + o0 + tx];
    __syncthreads();
#pragma unroll
    for (int r = 0; r < 32; r += 8) {
        float v = t[tx][ty + r];
        size_t idx = ((size_t)b * 128 + o0 + ty + r) * 2048 + j0 + tx;
        g_hT[idx] = __float2half_rn(v);
    }
}

// ---------------------------------------------------------------------------
// K2: s_src / s_dst
// ---------------------------------------------------------------------------
__global__ __launch_bounds__(256) void k2_s(const float* __restrict__ a) {
    const int warp = threadIdx.x >> 5, lane = threadIdx.x & 31;
    const int row = blockIdx.x * 8 + warp;
    const float* h = &g_h[(size_t)row * 128];
    float s1 = 0.f, s2 = 0.f;
#pragma unroll
    for (int t = 0; t < 4; t++) {
        float hv = h[lane + 32 * t];
        s1 += hv * a[lane + 32 * t];
        s2 += hv * a[128 + lane + 32 * t];
    }
#pragma unroll
    for (int off = 16; off > 0; off >>= 1) {
        s1 += __shfl_xor_sync(0xffffffffu, s1, off);
        s2 += __shfl_xor_sync(0xffffffffu, s2, off);
    }
    if (lane == 0) { g_ssrc[row] = s1; g_sdst[row] = s2; }
}

// ---------------------------------------------------------------------------
// K3: rank sort — 4 j per thread, 8 chunks of 256: 16 indep compares per LDS.128
// grid (16, 8), 256 threads
// ---------------------------------------------------------------------------
__global__ __launch_bounds__(256) void k3_sort() {
    __shared__ float s[2048];
    __shared__ int part[8][128];
    const int b = blockIdx.y;
    const int tid = threadIdx.x;  // 256
    for (int idx = tid; idx < 2048; idx += 256) s[idx] = g_sdst[b * 2048 + idx];
    __syncthreads();
    const int g = tid & 31;          // j-group (4 j's)
    const int ck = tid >> 5;         // chunk 0..7 (256 elems)
    const int jl0 = g * 4;
    const int jg0 = blockIdx.x * 128 + jl0;
    const float4 my = *(const float4*)&s[jg0];
    int r0 = 0, r1 = 0, r2 = 0, r3 = 0;
    const int q0 = ck * 256;
#pragma unroll 4
    for (int q = q0; q < q0 + 256; q += 4) {
#pragma unroll
        for (int e = 0; e < 4; e++) {
            float v = s[q + e];
            int qq = q + e;
            r0 += (v < my.x) || (v == my.x && qq < (jg0 + 0));
            r1 += (v < my.y) || (v == my.y && qq < (jg0 + 1));
            r2 += (v < my.z) || (v == my.z && qq < (jg0 + 2));
            r3 += (v < my.w) || (v == my.w && qq < (jg0 + 3));
        }
    }
    part[ck][jl0 + 0] = r0; part[ck][jl0 + 1] = r1;
    part[ck][jl0 + 2] = r2; part[ck][jl0 + 3] = r3;
    __syncthreads();
    if (tid < 128) {
        int r = 0;
#pragma unroll
        for (int c = 0; c < 8; c++) r += part[c][tid];
        const float mv = s[blockIdx.x * 128 + tid];
        const int base = b * 2048;
        g_v[base + r]    = mv;
        g_perm[base + r] = blockIdx.x * 128 + tid;
        g_w1[base + r]   = expf(mv);
        g_w02[base + r]  = expf(SLOPE * mv);
    }
}

// ---------------------------------------------------------------------------
// K4: fp32 chunked scans for numerator tables (grid (4,8), 1024 thr)
// ---------------------------------------------------------------------------
__global__ __launch_bounds__(1024) void k4_scanE() {
    __shared__ float cs1[32][33], cs02[32][33];
    __shared__ float off1A[32][32], off02A[32][32];
    __shared__ float tot1s[32];
    const int b = blockIdx.y;
    const int ol = threadIdx.x & 31;
    const int o = blockIdx.x * 32 + ol;
    const int c = threadIdx.x >> 5;
    const int base = b * 2048;
    const int r0 = c * 64;

    float a1 = 0.f, a02 = 0.f;
    for (int r = r0; r < r0 + 64; r++) {
        int j = g_perm[base + r];
        float hv = g_h[((size_t)(base + j)) * 128 + o];
        a1  += g_w1[base + r]  * hv;
        a02 += g_w02[base + r] * hv;
    }
    cs1[c][ol] = a1; cs02[c][ol] = a02;
    __syncthreads();
    if (c == 0) {
        float r1 = 0.f, r2 = 0.f;
        for (int q = 0; q < 32; q++) {
            off1A[q][ol] = r1;  r1 += cs1[q][ol];
            off02A[q][ol] = r2; r2 += cs02[q][ol];
        }
        tot1s[ol] = r1;
    }
    __syncthreads();
    float run1 = off1A[c][ol], run02 = off02A[c][ol];
    const float tot1 = tot1s[ol];
    const size_t tbase = ((size_t)b * 2049) * 128 + o;
    for (int r = r0; r < r0 + 64; r++) {
        int j = g_perm[base + r];
        float hv = g_h[((size_t)(base + j)) * 128 + o];
        g_suf1[tbase + (size_t)r * 128]  = tot1 - run1;
        run1 += g_w1[base + r] * hv;
        g_pre02[tbase + (size_t)r * 128] = run02;
        run02 += g_w02[base + r] * hv;
    }
    if (c == 31) {
        g_suf1[tbase + (size_t)2048 * 128]  = 0.f;
        g_pre02[tbase + (size_t)2048 * 128] = run02;
    }
}

// K4b: denominators (tiny, fp64)
__global__ __launch_bounds__(32) void k4b_scanD() {
    __shared__ double cs1[16], cs02[16], off1[16], off02[16], tot[2];
    const int b = blockIdx.x;
    const int c = threadIdx.x;
    const int base = b * 2048;
    if (c < 16) {
        double a1 = 0.0, a02 = 0.0;
        for (int r = c * 128; r < c * 128 + 128; r++) {
            a1 += (double)g_w1[base + r]; a02 += (double)g_w02[base + r];
        }
        cs1[c] = a1; cs02[c] = a02;
    }
    __syncthreads();
    if (c == 0) {
        double r1 = 0.0, r2 = 0.0;
        for (int q = 0; q < 16; q++) {
            off1[q] = r1; r1 += cs1[q];
            off02[q] = r2; r2 += cs02[q];
        }
        tot[0] = r1; tot[1] = r2;
    }
    __syncthreads();
    if (c < 16) {
        double run1 = off1[c], run02 = off02[c], t1 = tot[0];
        const size_t tb = (size_t)b * 2049;
        for (int r = c * 128; r < c * 128 + 128; r++) {
            g_sufD1[tb + r] = (float)(t1 - run1);
            run1 += (double)g_w1[base + r];
            g_preD02[tb + r] = (float)run02;
            run02 += (double)g_w02[base + r];
        }
        if (c == 15) { g_sufD1[tb + 2048] = 0.f; g_preD02[tb + 2048] = (float)run02; }
    }
}

// ---------------------------------------------------------------------------
// K5: single-term fp16 mma.sync GEMM (adj@h) + attention epilogue + lrelu
// CTA tile 128(i) x 128(o), K=2048 in 32 chunks of 64. 8 warps = 2(i) x 4(o).
// 2-stage pipeline; A: LDG fp32 -> fp16 convert -> STS; B: cp.async (fp16 hT).
// ---------------------------------------------------------------------------
#define TILE_B 18432u              // 128 x 144B
#define STG_BYTES (2u * TILE_B)    // A + B tiles
#define OFF_A 0u
#define OFF_B TILE_B
#define K5_SMEM (2 * STG_BYTES)

__global__ __launch_bounds__(256) void k5_main(const float* __restrict__ adj,
                                               float* __restrict__ out) {
    extern __shared__ __align__(128) char dsm[];
    __shared__ int kS[128];
    __shared__ float e1S[128], e02S[128], dinvS[128];
    const uint32_t sb = smem_u32(dsm);
    const int tid = threadIdx.x;
    const int b = blockIdx.y;
    const int i0 = blockIdx.x * 128;

    // --- binary-search setup (uses dynamic smem as temp before tiles) ---
    {
        float* vS = (float*)dsm;
        for (int idx = tid; idx < 2048; idx += 256) vS[idx] = g_v[b * 2048 + idx];
        __syncthreads();
        if (tid < 128) {
            float si = g_ssrc[b * 2048 + i0 + tid];
            float target = -si;
            int lo = 0, hi = 2048;
            while (lo < hi) { int mid = (lo + hi) >> 1; if (vS[mid] < target) lo = mid + 1; else hi = mid; }
            float e1 = expf(si), e02 = expf(SLOPE * si);
            float Dv = e1 * g_sufD1[(size_t)b * 2049 + lo] + e02 * g_preD02[(size_t)b * 2049 + lo];
            kS[tid] = lo; e1S[tid] = e1; e02S[tid] = e02; dinvS[tid] = 1.0f / Dv;
        }
        __syncthreads();
    }

    // loader mapping: row = tid>>1 (0..127), half = tid&1 (32-col subchunk)
    const int row = tid >> 1, half = tid & 1;
    const float* aRow = adj + ((size_t)(b * 2048 + i0 + row)) * 2048 + half * 32;
    const __half* hRow = g_hT + ((size_t)(b * 128 + row)) * 2048 + half * 32;
    const uint32_t stsBase = (uint32_t)row * 144 + (uint32_t)half * 64;

    // compute mapping: warp -> (wi in {0,1}, wo in {0..3})
    const int warp = tid >> 5, lane = tid & 31;
    const int wi = warp & 1, wo = warp >> 1;
    const int obase = wo * 32;
    const uint32_t aLane = (uint32_t)(wi * 64 + (lane & 15)) * 144 + ((lane >> 4) << 4);
    const uint32_t bLane = (uint32_t)(obase + (lane & 7) + ((lane & 16) >> 1)) * 144 + ((lane & 8) << 1);

    float acc[4][4][4];
#pragma unroll
    for (int mf = 0; mf < 4; mf++)
#pragma unroll
        for (int nf = 0; nf < 4; nf++)
#pragma unroll
            for (int e = 0; e < 4; e++) acc[mf][nf][e] = 0.f;

    // ---- prologue: stage 0 <- chunk 0 ----
    {
#pragma unroll
        for (int p = 0; p < 4; p++)
            cp16(sb + OFF_B + stsBase + p * 16, hRow + p * 8);
        CP_COMMIT();
#pragma unroll
        for (int p = 0; p < 4; p++) {
            float4 u = *(const float4*)(aRow + p * 8);
            float4 w = *(const float4*)(aRow + p * 8 + 4);
            sts128(sb + OFF_A + stsBase + p * 16,
                   cvt2h(u.y, u.x), cvt2h(u.w, u.z), cvt2h(w.y, w.x), cvt2h(w.w, w.z));
        }
        CP_WAIT0();
        __syncthreads();
    }

    for (int c = 0; c < 32; c++) {
        const uint32_t sCur = sb + (c & 1 ? STG_BYTES : 0u);
        const uint32_t sNxt = sb + (c & 1 ? 0u : STG_BYTES);
        const int j1 = (c + 1) * 64;
        float4 fA[8];
        if (c < 31) {
#pragma unroll
            for (int p = 0; p < 4; p++)
                cp16(sNxt + OFF_B + stsBase + p * 16, hRow + j1 + p * 8);
            CP_COMMIT();
#pragma unroll
            for (int p = 0; p < 8; p++) fA[p] = *(const float4*)(aRow + j1 + p * 4);
        }
        // ---- compute current chunk: 4 k16 steps ----
#pragma unroll
        for (int kk = 0; kk < 4; kk++) {
            uint32_t aF[4][4], bF[8];
            const uint32_t aAddr = sCur + OFF_A + aLane + kk * 32;
            const uint32_t bAddr = sCur + OFF_B + bLane + kk * 32;
#pragma unroll
            for (int mf = 0; mf < 4; mf++)
                ldmx4(aF[mf], aAddr + mf * (16 * 144));
            ldmx4(&bF[0], bAddr);
            ldmx4(&bF[4], bAddr + 16 * 144);
#pragma unroll
            for (int mf = 0; mf < 4; mf++)
#pragma unroll
                for (int nf = 0; nf < 4; nf++)
                    mma16816(acc[mf][nf], aF[mf], &bF[nf * 2]);
        }
        if (c < 31) {
#pragma unroll
            for (int p = 0; p < 4; p++) {
                float4 u = fA[p * 2], w = fA[p * 2 + 1];
                sts128(sNxt + OFF_A + stsBase + p * 16,
                       cvt2h(u.y, u.x), cvt2h(u.w, u.z), cvt2h(w.y, w.x), cvt2h(w.w, w.z));
            }
        }
        CP_WAIT0();
        __syncthreads();
    }

    // ---- epilogue: attention lookup + lrelu + store ----
#pragma unroll
    for (int mf = 0; mf < 4; mf++) {
        const int rl0 = wi * 64 + mf * 16 + (lane >> 2);
#pragma unroll
        for (int hh = 0; hh < 2; hh++) {
            const int rl = rl0 + hh * 8;
            const int k = kS[rl];
            const float e1 = e1S[rl], e02 = e02S[rl], dinv = dinvS[rl];
            const float* suf = &g_suf1[((size_t)(b * 2049 + k)) * 128];
            const float* pre = &g_pre02[((size_t)(b * 2049 + k)) * 128];
            float* dst = &out[((size_t)(b * 2048 + i0 + rl)) * 128];
#pragma unroll
            for (int nf = 0; nf < 4; nf++) {
                const int o = obase + nf * 8 + (lane & 3) * 2;
                float2 sf = *(const float2*)&suf[o];
                float2 pf = *(const float2*)&pre[o];
                float v0 = acc[mf][nf][hh * 2 + 0] + (e1 * sf.x + e02 * pf.x) * dinv;
                float v1 = acc[mf][nf][hh * 2 + 1] + (e1 * sf.y + e02 * pf.y) * dinv;
                float2 r;
                r.x = v0 >= 0.f ? v0 : SLOPE * v0;
                r.y = v1 >= 0.f ? v1 : SLOPE * v1;
                *(float2*)&dst[o] = r;
            }
        }
    }
}

// ---------------------------------------------------------------------------
extern "C" void kernel_launch(void* const* d_in, const int* in_sizes, int n_in,
                              void* d_out, int out_size) {
    (void)in_sizes; (void)n_in; (void)out_size;
    const float* x   = (const float*)d_in[0];
    const float* adj = (const float*)d_in[1];
    const float* W   = (const float*)d_in[2];
    const float* a   = (const float*)d_in[3];
    float* out = (float*)d_out;

    cudaFuncSetAttribute(k5_main, cudaFuncAttributeMaxDynamicSharedMemorySize, K5_SMEM);

    k1_xw<<<256, 256>>>(x, W);
    k1b_split<<<dim3(64, 4, 8), dim3(32, 8)>>>();
    k2_s<<<2048, 256>>>(a);
    k3_sort<<<dim3(16, 8), 256>>>();
    k4_scanE<<<dim3(4, 8), 1024>>>();
    k4b_scanD<<<8, 32>>>();
    k5_main<<<dim3(16, 8), 256, K5_SMEM>>>(adj, out);
}

// round 11
// speedup vs baseline: 1.9283x; 1.3380x over previous
#include <cuda_runtime.h>
#include <cuda_fp16.h>
#include <math.h>
#include <stdint.h>

#define SLOPE 0.2f

// Shapes fixed: B=8, N=2048, D=128.
__device__ float g_h[8 * 2048 * 128];     // h = x @ W (fp32)
__device__ __half g_hT[8 * 128 * 2048];   // fp16 h, transposed [b][o][j]
__device__ float g_ssrc[8 * 2048];
__device__ float g_sdst[8 * 2048];
__device__ float g_v[8 * 2048];
__device__ int   g_perm[8 * 2048];
__device__ float g_w1[8 * 2048];
__device__ float g_w02[8 * 2048];
__device__ float g_suf1[8 * 2049 * 128];
__device__ float g_pre02[8 * 2049 * 128];
__device__ float g_sufD1[8 * 2049];
__device__ float g_preD02[8 * 2049];

// ---------------------------------------------------------------------------
// helpers
// ---------------------------------------------------------------------------
__device__ __forceinline__ uint32_t smem_u32(const void* p) {
    uint32_t a;
    asm("{ .reg .u64 t; cvta.to.shared.u64 t, %1; cvt.u32.u64 %0, t; }" : "=r"(a) : "l"(p));
    return a;
}
__device__ __forceinline__ void ldmx4(uint32_t* r, uint32_t addr) {
    asm volatile("ldmatrix.sync.aligned.m8n8.x4.shared.b16 {%0,%1,%2,%3}, [%4];"
                 : "=r"(r[0]), "=r"(r[1]), "=r"(r[2]), "=r"(r[3]) : "r"(addr));
}
__device__ __forceinline__ void mma16816(float* d, const uint32_t* a, const uint32_t* b) {
    asm volatile(
        "mma.sync.aligned.m16n8k16.row.col.f32.f16.f16.f32 "
        "{%0,%1,%2,%3}, {%4,%5,%6,%7}, {%8,%9}, {%0,%1,%2,%3};"
        : "+f"(d[0]), "+f"(d[1]), "+f"(d[2]), "+f"(d[3])
        : "r"(a[0]), "r"(a[1]), "r"(a[2]), "r"(a[3]), "r"(b[0]), "r"(b[1]));
}
__device__ __forceinline__ void cp16(uint32_t dst, const void* src) {
    asm volatile("cp.async.cg.shared.global [%0], [%1], 16;" :: "r"(dst), "l"(src));
}
#define CP_COMMIT() asm volatile("cp.async.commit_group;" ::: "memory")
#define CP_WAIT0()  asm volatile("cp.async.wait_group 0;" ::: "memory")

__device__ __forceinline__ uint32_t cvt2h(float hi, float lo) {
    uint32_t r;
    asm("cvt.rn.f16x2.f32 %0, %1, %2;" : "=r"(r) : "f"(hi), "f"(lo));
    return r;
}
__device__ __forceinline__ void sts64(uint32_t a, uint32_t x, uint32_t y) {
    asm volatile("st.shared.v2.b32 [%0], {%1,%2};" :: "r"(a), "r"(x), "r"(y) : "memory");
}

// ---------------------------------------------------------------------------
// K1: h = x @ W
// ---------------------------------------------------------------------------
__global__ __launch_bounds__(256) void k1_xw(const float* __restrict__ x,
                                             const float* __restrict__ W) {
    __shared__ float xs[64][33];
    __shared__ float Ws[32][128];
    const int tid = threadIdx.x;
    const int row0 = blockIdx.x * 64;
    const int ig = tid >> 4, og = tid & 15;
    const int iBase = ig * 4, oBase = og * 8;
    float acc[4][8];
#pragma unroll
    for (int a = 0; a < 4; a++)
#pragma unroll
        for (int c = 0; c < 8; c++) acc[a][c] = 0.f;

    const int seg = tid & 7, r = tid >> 3;
    for (int k0 = 0; k0 < 128; k0 += 32) {
#pragma unroll
        for (int p = 0; p < 2; p++) {
            int rr = r + p * 32;
            float4 v = *(const float4*)&x[(size_t)(row0 + rr) * 128 + k0 + seg * 4];
            xs[rr][seg * 4 + 0] = v.x; xs[rr][seg * 4 + 1] = v.y;
            xs[rr][seg * 4 + 2] = v.z; xs[rr][seg * 4 + 3] = v.w;
        }
        for (int idx = tid; idx < 32 * 128 / 4; idx += 256)
            *(float4*)(&Ws[0][0] + idx * 4) = *(const float4*)&W[(size_t)k0 * 128 + idx * 4];
        __syncthreads();
#pragma unroll 8
        for (int kk = 0; kk < 32; kk++) {
            float a0 = xs[iBase + 0][kk], a1 = xs[iBase + 1][kk];
            float a2 = xs[iBase + 2][kk], a3 = xs[iBase + 3][kk];
            float bv[8];
            *(float4*)&bv[0] = *(const float4*)&Ws[kk][oBase];
            *(float4*)&bv[4] = *(const float4*)&Ws[kk][oBase + 4];
#pragma unroll
            for (int c = 0; c < 8; c++) {
                acc[0][c] += a0 * bv[c];
                acc[1][c] += a1 * bv[c];
                acc[2][c] += a2 * bv[c];
                acc[3][c] += a3 * bv[c];
            }
        }
        __syncthreads();
    }
#pragma unroll
    for (int a = 0; a < 4; a++) {
        float* dst = &g_h[(size_t)(row0 + iBase + a) * 128 + oBase];
        *(float4*)&dst[0] = make_float4(acc[a][0], acc[a][1], acc[a][2], acc[a][3]);
        *(float4*)&dst[4] = make_float4(acc[a][4], acc[a][5], acc[a][6], acc[a][7]);
    }
}

// ---------------------------------------------------------------------------
// K1b: transpose h -> [b][o][j], convert to fp16
// ---------------------------------------------------------------------------
__global__ __launch_bounds__(256) void k1b_split() {
    __shared__ float t[32][33];
    const int b = blockIdx.z;
    const int j0 = blockIdx.x * 32, o0 = blockIdx.y * 32;
    const int tx = threadIdx.x, ty = threadIdx.y;  // 32 x 8
#pragma unroll
    for (int r = 0; r < 32; r += 8)
        t[ty + r][tx] = g_h[((size_t)b * 2048 + j0 + ty + r) * 128 + o0 + tx];
    __syncthreads();
#pragma unroll
    for (int r = 0; r < 32; r += 8) {
        float v = t[tx][ty + r];
        size_t idx = ((size_t)b * 128 + o0 + ty + r) * 2048 + j0 + tx;
        g_hT[idx] = __float2half_rn(v);
    }
}

// ---------------------------------------------------------------------------
// K2: s_src / s_dst
// ---------------------------------------------------------------------------
__global__ __launch_bounds__(256) void k2_s(const float* __restrict__ a) {
    const int warp = threadIdx.x >> 5, lane = threadIdx.x & 31;
    const int row = blockIdx.x * 8 + warp;
    const float* h = &g_h[(size_t)row * 128];
    float s1 = 0.f, s2 = 0.f;
#pragma unroll
    for (int t = 0; t < 4; t++) {
        float hv = h[lane + 32 * t];
        s1 += hv * a[lane + 32 * t];
        s2 += hv * a[128 + lane + 32 * t];
    }
#pragma unroll
    for (int off = 16; off > 0; off >>= 1) {
        s1 += __shfl_xor_sync(0xffffffffu, s1, off);
        s2 += __shfl_xor_sync(0xffffffffu, s2, off);
    }
    if (lane == 0) { g_ssrc[row] = s1; g_sdst[row] = s2; }
}

// ---------------------------------------------------------------------------
// K3: rank sort — 512 thr: 4 j per thread-group, 16 chunks of 128, float4 LDS
// ---------------------------------------------------------------------------
__global__ __launch_bounds__(512) void k3_sort() {
    __shared__ float s[2048];
    __shared__ int part[16][128];
    const int b = blockIdx.y;
    const int tid = threadIdx.x;  // 512
    for (int idx = tid; idx < 2048; idx += 512) s[idx] = g_sdst[b * 2048 + idx];
    __syncthreads();
    const int g = tid & 31;          // j-group (4 j's)
    const int ck = tid >> 5;         // chunk 0..15 (128 elems)
    const int jl0 = g * 4;
    const int jg0 = blockIdx.x * 128 + jl0;
    const float4 my = *(const float4*)&s[jg0];
    int r0 = 0, r1 = 0, r2 = 0, r3 = 0;
    const int q0 = ck * 128;
#pragma unroll 8
    for (int q = q0; q < q0 + 128; q += 4) {
        const float4 v = *(const float4*)&s[q];
        r0 += (v.x < my.x) || (v.x == my.x && (q + 0) < (jg0 + 0));
        r1 += (v.x < my.y) || (v.x == my.y && (q + 0) < (jg0 + 1));
        r2 += (v.x < my.z) || (v.x == my.z && (q + 0) < (jg0 + 2));
        r3 += (v.x < my.w) || (v.x == my.w && (q + 0) < (jg0 + 3));
        r0 += (v.y < my.x) || (v.y == my.x && (q + 1) < (jg0 + 0));
        r1 += (v.y < my.y) || (v.y == my.y && (q + 1) < (jg0 + 1));
        r2 += (v.y < my.z) || (v.y == my.z && (q + 1) < (jg0 + 2));
        r3 += (v.y < my.w) || (v.y == my.w && (q + 1) < (jg0 + 3));
        r0 += (v.z < my.x) || (v.z == my.x && (q + 2) < (jg0 + 0));
        r1 += (v.z < my.y) || (v.z == my.y && (q + 2) < (jg0 + 1));
        r2 += (v.z < my.z) || (v.z == my.z && (q + 2) < (jg0 + 2));
        r3 += (v.z < my.w) || (v.z == my.w && (q + 2) < (jg0 + 3));
        r0 += (v.w < my.x) || (v.w == my.x && (q + 3) < (jg0 + 0));
        r1 += (v.w < my.y) || (v.w == my.y && (q + 3) < (jg0 + 1));
        r2 += (v.w < my.z) || (v.w == my.z && (q + 3) < (jg0 + 2));
        r3 += (v.w < my.w) || (v.w == my.w && (q + 3) < (jg0 + 3));
    }
    part[ck][jl0 + 0] = r0; part[ck][jl0 + 1] = r1;
    part[ck][jl0 + 2] = r2; part[ck][jl0 + 3] = r3;
    __syncthreads();
    if (tid < 128) {
        int r = 0;
#pragma unroll
        for (int c = 0; c < 16; c++) r += part[c][tid];
        const float mv = s[blockIdx.x * 128 + tid];
        const int base = b * 2048;
        g_v[base + r]    = mv;
        g_perm[base + r] = blockIdx.x * 128 + tid;
        g_w1[base + r]   = expf(mv);
        g_w02[base + r]  = expf(SLOPE * mv);
    }
}

// ---------------------------------------------------------------------------
// K4: fp32 chunked scans for numerator tables (grid (4,8), 1024 thr)
// ---------------------------------------------------------------------------
__global__ __launch_bounds__(1024) void k4_scanE() {
    __shared__ float cs1[32][33], cs02[32][33];
    __shared__ float off1A[32][32], off02A[32][32];
    __shared__ float tot1s[32];
    const int b = blockIdx.y;
    const int ol = threadIdx.x & 31;
    const int o = blockIdx.x * 32 + ol;
    const int c = threadIdx.x >> 5;
    const int base = b * 2048;
    const int r0 = c * 64;

    float a1 = 0.f, a02 = 0.f;
    for (int r = r0; r < r0 + 64; r++) {
        int j = g_perm[base + r];
        float hv = g_h[((size_t)(base + j)) * 128 + o];
        a1  += g_w1[base + r]  * hv;
        a02 += g_w02[base + r] * hv;
    }
    cs1[c][ol] = a1; cs02[c][ol] = a02;
    __syncthreads();
    if (c == 0) {
        float r1 = 0.f, r2 = 0.f;
        for (int q = 0; q < 32; q++) {
            off1A[q][ol] = r1;  r1 += cs1[q][ol];
            off02A[q][ol] = r2; r2 += cs02[q][ol];
        }
        tot1s[ol] = r1;
    }
    __syncthreads();
    float run1 = off1A[c][ol], run02 = off02A[c][ol];
    const float tot1 = tot1s[ol];
    const size_t tbase = ((size_t)b * 2049) * 128 + o;
    for (int r = r0; r < r0 + 64; r++) {
        int j = g_perm[base + r];
        float hv = g_h[((size_t)(base + j)) * 128 + o];
        g_suf1[tbase + (size_t)r * 128]  = tot1 - run1;
        run1 += g_w1[base + r] * hv;
        g_pre02[tbase + (size_t)r * 128] = run02;
        run02 += g_w02[base + r] * hv;
    }
    if (c == 31) {
        g_suf1[tbase + (size_t)2048 * 128]  = 0.f;
        g_pre02[tbase + (size_t)2048 * 128] = run02;
    }
}

// K4b: denominators (tiny, fp64)
__global__ __launch_bounds__(32) void k4b_scanD() {
    __shared__ double cs1[16], cs02[16], off1[16], off02[16], tot[2];
    const int b = blockIdx.x;
    const int c = threadIdx.x;
    const int base = b * 2048;
    if (c < 16) {
        double a1 = 0.0, a02 = 0.0;
        for (int r = c * 128; r < c * 128 + 128; r++) {
            a1 += (double)g_w1[base + r]; a02 += (double)g_w02[base + r];
        }
        cs1[c] = a1; cs02[c] = a02;
    }
    __syncthreads();
    if (c == 0) {
        double r1 = 0.0, r2 = 0.0;
        for (int q = 0; q < 16; q++) {
            off1[q] = r1; r1 += cs1[q];
            off02[q] = r2; r2 += cs02[q];
        }
        tot[0] = r1; tot[1] = r2;
    }
    __syncthreads();
    if (c < 16) {
        double run1 = off1[c], run02 = off02[c], t1 = tot[0];
        const size_t tb = (size_t)b * 2049;
        for (int r = c * 128; r < c * 128 + 128; r++) {
            g_sufD1[tb + r] = (float)(t1 - run1);
            run1 += (double)g_w1[base + r];
            g_preD02[tb + r] = (float)run02;
            run02 += (double)g_w02[base + r];
        }
        if (c == 15) { g_sufD1[tb + 2048] = 0.f; g_preD02[tb + 2048] = (float)run02; }
    }
}

// ---------------------------------------------------------------------------
// K5: fp16 mma.sync GEMM (adj@h) + attention epilogue + lrelu
// 512 thr, 16 warps = 4(i) x 4(o), warp tile 32x32. CTA 128x128, K-chunk 128
// (16 chunks). Coalesced loaders: A warp-LDG = contiguous 512B row segment;
// B cp.async 16 thr/row. SMEM rows 272B (17x16B, ldmatrix conflict-free).
// ---------------------------------------------------------------------------
#define AROW 272u
#define TILE_BYTES (128u * AROW)     // 34816
#define OFF_A 0u
#define OFF_B TILE_BYTES
#define STG_BYTES (2u * TILE_BYTES)  // 69632
#define K5_SMEM (2u * STG_BYTES)     // 139264

__global__ __launch_bounds__(512) void k5_main(const float* __restrict__ adj,
                                               float* __restrict__ out) {
    extern __shared__ __align__(128) char dsm[];
    __shared__ int kS[128];
    __shared__ float e1S[128], e02S[128], dinvS[128];
    const uint32_t sb = smem_u32(dsm);
    const int tid = threadIdx.x;
    const int b = blockIdx.y;
    const int i0 = blockIdx.x * 128;

    // --- binary-search setup (uses dynamic smem as temp before tiles) ---
    {
        float* vS = (float*)dsm;
        for (int idx = tid; idx < 2048; idx += 512) vS[idx] = g_v[b * 2048 + idx];
        __syncthreads();
        if (tid < 128) {
            float si = g_ssrc[b * 2048 + i0 + tid];
            float target = -si;
            int lo = 0, hi = 2048;
            while (lo < hi) { int mid = (lo + hi) >> 1; if (vS[mid] < target) lo = mid + 1; else hi = mid; }
            float e1 = expf(si), e02 = expf(SLOPE * si);
            float Dv = e1 * g_sufD1[(size_t)b * 2049 + lo] + e02 * g_preD02[(size_t)b * 2049 + lo];
            kS[tid] = lo; e1S[tid] = e1; e02S[tid] = e02; dinvS[tid] = 1.0f / Dv;
        }
        __syncthreads();
    }

    const int warp = tid >> 5, lane = tid & 31;

    // A loader: pass p (0..7): row = p*16 + warp, col4 = lane (32 float4 = 512B)
    const float* adjT = adj + ((size_t)(b * 2048 + i0)) * 2048;
    const uint32_t aStsBase = (uint32_t)warp * AROW + (uint32_t)lane * 8;  // + p*16*AROW
    // B loader: pass p (0..3): idx = p*512+tid: row = idx>>4, seg = idx&15
    const __half* hTb = g_hT + ((size_t)b * 128) * 2048;

    // compute mapping: warp -> (wi 0..3, wo 0..3)
    const int wi = warp & 3, wo = warp >> 2;
    const int obase = wo * 32;
    const uint32_t aLane = (uint32_t)(wi * 32 + (lane & 15)) * AROW + ((lane >> 4) << 4);
    const uint32_t bLane = (uint32_t)(obase + (lane & 7) + ((lane & 16) >> 1)) * AROW + ((lane & 8) << 1);

    float acc[2][4][4];
#pragma unroll
    for (int mf = 0; mf < 2; mf++)
#pragma unroll
        for (int nf = 0; nf < 4; nf++)
#pragma unroll
            for (int e = 0; e < 4; e++) acc[mf][nf][e] = 0.f;

    // ---- prologue: chunk 0 -> stage 0 ----
    {
#pragma unroll
        for (int p = 0; p < 4; p++) {
            int idx = p * 512 + tid;
            int brow = idx >> 4, seg = idx & 15;
            cp16(sb + OFF_B + (uint32_t)brow * AROW + (uint32_t)seg * 16,
                 hTb + (size_t)brow * 2048 + seg * 8);
        }
        CP_COMMIT();
#pragma unroll
        for (int p = 0; p < 8; p++) {
            int arow = p * 16 + warp;
            float4 u = *(const float4*)(adjT + (size_t)arow * 2048 + lane * 4);
            sts64(sb + OFF_A + aStsBase + (uint32_t)p * (16u * AROW),
                  cvt2h(u.y, u.x), cvt2h(u.w, u.z));
        }
        CP_WAIT0();
        __syncthreads();
    }

    for (int c = 0; c < 16; c++) {
        const uint32_t sCur = sb + (c & 1 ? STG_BYTES : 0u);
        const uint32_t sNxt = sb + (c & 1 ? 0u : STG_BYTES);
        const int j1 = (c + 1) * 128;
        float4 fA[8];
        if (c < 15) {
#pragma unroll
            for (int p = 0; p < 4; p++) {
                int idx = p * 512 + tid;
                int brow = idx >> 4, seg = idx & 15;
                cp16(sNxt + OFF_B + (uint32_t)brow * AROW + (uint32_t)seg * 16,
                     hTb + (size_t)brow * 2048 + j1 + seg * 8);
            }
            CP_COMMIT();
#pragma unroll
            for (int p = 0; p < 8; p++) {
                int arow = p * 16 + warp;
                fA[p] = *(const float4*)(adjT + (size_t)arow * 2048 + j1 + lane * 4);
            }
        }
        // ---- compute current chunk: 8 k16 steps ----
#pragma unroll
        for (int kk = 0; kk < 8; kk++) {
            uint32_t aF[2][4], bF[8];
            const uint32_t aAddr = sCur + OFF_A + aLane + kk * 32;
            const uint32_t bAddr = sCur + OFF_B + bLane + kk * 32;
            ldmx4(aF[0], aAddr);
            ldmx4(aF[1], aAddr + 16u * AROW);
            ldmx4(&bF[0], bAddr);
            ldmx4(&bF[4], bAddr + 16u * AROW);
#pragma unroll
            for (int mf = 0; mf < 2; mf++)
#pragma unroll
                for (int nf = 0; nf < 4; nf++)
                    mma16816(acc[mf][nf], aF[mf], &bF[nf * 2]);
        }
        if (c < 15) {
#pragma unroll
            for (int p = 0; p < 8; p++) {
                float4 u = fA[p];
                sts64(sNxt + OFF_A + aStsBase + (uint32_t)p * (16u * AROW),
                      cvt2h(u.y, u.x), cvt2h(u.w, u.z));
            }
        }
        CP_WAIT0();
        __syncthreads();
    }

    // ---- epilogue: attention lookup + lrelu + store ----
#pragma unroll
    for (int mf = 0; mf < 2; mf++) {
        const int rl0 = wi * 32 + mf * 16 + (lane >> 2);
#pragma unroll
        for (int hh = 0; hh < 2; hh++) {
            const int rl = rl0 + hh * 8;
            const int k = kS[rl];
            const float e1 = e1S[rl], e02 = e02S[rl], dinv = dinvS[rl];
            const float* suf = &g_suf1[((size_t)(b * 2049 + k)) * 128];
            const float* pre = &g_pre02[((size_t)(b * 2049 + k)) * 128];
            float* dst = &out[((size_t)(b * 2048 + i0 + rl)) * 128];
#pragma unroll
            for (int nf = 0; nf < 4; nf++) {
                const int o = obase + nf * 8 + (lane & 3) * 2;
                float2 sf = *(const float2*)&suf[o];
                float2 pf = *(const float2*)&pre[o];
                float v0 = acc[mf][nf][hh * 2 + 0] + (e1 * sf.x + e02 * pf.x) * dinv;
                float v1 = acc[mf][nf][hh * 2 + 1] + (e1 * sf.y + e02 * pf.y) * dinv;
                float2 r;
                r.x = v0 >= 0.f ? v0 : SLOPE * v0;
                r.y = v1 >= 0.f ? v1 : SLOPE * v1;
                *(float2*)&dst[o] = r;
            }
        }
    }
}

// ---------------------------------------------------------------------------
extern "C" void kernel_launch(void* const* d_in, const int* in_sizes, int n_in,
                              void* d_out, int out_size) {
    (void)in_sizes; (void)n_in; (void)out_size;
    const float* x   = (const float*)d_in[0];
    const float* adj = (const float*)d_in[1];
    const float* W   = (const float*)d_in[2];
    const float* a   = (const float*)d_in[3];
    float* out = (float*)d_out;

    cudaFuncSetAttribute(k5_main, cudaFuncAttributeMaxDynamicSharedMemorySize, K5_SMEM);

    k1_xw<<<256, 256>>>(x, W);
    k1b_split<<<dim3(64, 4, 8), dim3(32, 8)>>>();
    k2_s<<<2048, 256>>>(a);
    k3_sort<<<dim3(16, 8), 512>>>();
    k4_scanE<<<dim3(4, 8), 1024>>>();
    k4b_scanD<<<8, 32>>>();
    k5_main<<<dim3(16, 8), 512, K5_SMEM>>>(adj, out);
}

// round 12
// speedup vs baseline: 2.1731x; 1.1270x over previous
#include <cuda_runtime.h>
#include <cuda_fp16.h>
#include <math.h>
#include <stdint.h>

#define SLOPE 0.2f
#define AROW 272u

// Shapes fixed: B=8, N=2048, D=128.
__device__ float g_h[8 * 2048 * 128];     // h = x @ W (fp32)
__device__ __half g_hT[8 * 128 * 2048];   // fp16 h, transposed [b][o][j]
__device__ __half g_WT[128 * 128];        // fp16 W^T [o][k]
__device__ float g_ssrc[8 * 2048];
__device__ float g_sdst[8 * 2048];
__device__ float g_v[8 * 2048];
__device__ int   g_perm[8 * 2048];
__device__ float g_w1[8 * 2048];
__device__ float g_w02[8 * 2048];
__device__ float g_suf1[8 * 2049 * 128];
__device__ float g_pre02[8 * 2049 * 128];
__device__ float g_sufD1[8 * 2049];
__device__ float g_preD02[8 * 2049];

// ---------------------------------------------------------------------------
// helpers
// ---------------------------------------------------------------------------
__device__ __forceinline__ uint32_t smem_u32(const void* p) {
    uint32_t a;
    asm("{ .reg .u64 t; cvta.to.shared.u64 t, %1; cvt.u32.u64 %0, t; }" : "=r"(a) : "l"(p));
    return a;
}
__device__ __forceinline__ void ldmx4(uint32_t* r, uint32_t addr) {
    asm volatile("ldmatrix.sync.aligned.m8n8.x4.shared.b16 {%0,%1,%2,%3}, [%4];"
                 : "=r"(r[0]), "=r"(r[1]), "=r"(r[2]), "=r"(r[3]) : "r"(addr));
}
__device__ __forceinline__ void mma16816(float* d, const uint32_t* a, const uint32_t* b) {
    asm volatile(
        "mma.sync.aligned.m16n8k16.row.col.f32.f16.f16.f32 "
        "{%0,%1,%2,%3}, {%4,%5,%6,%7}, {%8,%9}, {%0,%1,%2,%3};"
        : "+f"(d[0]), "+f"(d[1]), "+f"(d[2]), "+f"(d[3])
        : "r"(a[0]), "r"(a[1]), "r"(a[2]), "r"(a[3]), "r"(b[0]), "r"(b[1]));
}
__device__ __forceinline__ uint32_t cvt2h(float hi, float lo) {
    uint32_t r;
    asm("cvt.rn.f16x2.f32 %0, %1, %2;" : "=r"(r) : "f"(hi), "f"(lo));
    return r;
}
__device__ __forceinline__ void sts128(uint32_t a, uint32_t x, uint32_t y, uint32_t z, uint32_t w) {
    asm volatile("st.shared.v4.b32 [%0], {%1,%2,%3,%4};" :: "r"(a), "r"(x), "r"(y), "r"(z), "r"(w) : "memory");
}

// ---------------------------------------------------------------------------
// K0: W [k][o] fp32 -> g_WT [o][k] fp16  (tiny, one-shot)
// ---------------------------------------------------------------------------
__global__ __launch_bounds__(256) void k0_wt(const float* __restrict__ W) {
    __shared__ float t[32][33];
    const int k0 = blockIdx.x * 32, o0 = blockIdx.y * 32;
    const int tx = threadIdx.x, ty = threadIdx.y;  // 32 x 8
#pragma unroll
    for (int r = 0; r < 32; r += 8)
        t[ty + r][tx] = W[(size_t)(k0 + ty + r) * 128 + o0 + tx];
    __syncthreads();
#pragma unroll
    for (int r = 0; r < 32; r += 8)
        g_WT[(size_t)(o0 + ty + r) * 128 + k0 + tx] = __float2half_rn(t[tx][ty + r]);
}

// ---------------------------------------------------------------------------
// K1: h = x @ W via fp16 mma.sync (x converted in-kernel, WT pre-built)
// grid 128 CTAs (128 rows each), 256 thr = 8 warps (2 wi x 4 wo), warp 64x32
// ---------------------------------------------------------------------------
#define K1_TILE (128u * AROW)           // 34816
#define K1_SMEM (2u * K1_TILE)          // 69632

__global__ __launch_bounds__(256) void k1_mma(const float* __restrict__ x) {
    extern __shared__ __align__(128) char dsm[];
    const uint32_t sb = smem_u32(dsm);
    const uint32_t OFF_X = 0u, OFF_W = K1_TILE;
    const int tid = threadIdx.x;
    const size_t i0 = (size_t)blockIdx.x * 128;

    // load WT (32KB fp16) -> SMEM [o][k], 272B rows
    {
#pragma unroll
        for (int p = 0; p < 8; p++) {
            int idx = p * 256 + tid;
            int brow = idx >> 4, seg = idx & 15;
            uint4 v = *(const uint4*)(g_WT + (size_t)brow * 128 + seg * 8);
            sts128(sb + OFF_W + (uint32_t)brow * AROW + (uint32_t)seg * 16, v.x, v.y, v.z, v.w);
        }
    }
    // load x tile (128x128 fp32) -> cvt fp16 -> SMEM
    {
        const int row = tid >> 1, half = tid & 1;
        const float* xr = x + (i0 + row) * 128 + half * 64;
        const uint32_t sBase = sb + OFF_X + (uint32_t)row * AROW + (uint32_t)half * 128;
#pragma unroll
        for (int p = 0; p < 8; p++) {
            float4 u = *(const float4*)(xr + p * 8);
            float4 w = *(const float4*)(xr + p * 8 + 4);
            sts128(sBase + p * 16, cvt2h(u.y, u.x), cvt2h(u.w, u.z),
                   cvt2h(w.y, w.x), cvt2h(w.w, w.z));
        }
    }
    __syncthreads();

    const int warp = tid >> 5, lane = tid & 31;
    const int wi = warp & 1, wo = warp >> 1;
    const int obase = wo * 32;
    const uint32_t aLane = (uint32_t)(wi * 64 + (lane & 15)) * AROW + ((lane >> 4) << 4);
    const uint32_t bLane = (uint32_t)(obase + (lane & 7) + ((lane & 16) >> 1)) * AROW + ((lane & 8) << 1);

    float acc[4][4][4];
#pragma unroll
    for (int mf = 0; mf < 4; mf++)
#pragma unroll
        for (int nf = 0; nf < 4; nf++)
#pragma unroll
            for (int e = 0; e < 4; e++) acc[mf][nf][e] = 0.f;

#pragma unroll
    for (int kk = 0; kk < 8; kk++) {
        uint32_t aF[4][4], bF[8];
        const uint32_t aAddr = sb + OFF_X + aLane + kk * 32;
        const uint32_t bAddr = sb + OFF_W + bLane + kk * 32;
#pragma unroll
        for (int mf = 0; mf < 4; mf++) ldmx4(aF[mf], aAddr + (uint32_t)mf * (16u * AROW));
        ldmx4(&bF[0], bAddr);
        ldmx4(&bF[4], bAddr + 16u * AROW);
#pragma unroll
        for (int mf = 0; mf < 4; mf++)
#pragma unroll
            for (int nf = 0; nf < 4; nf++)
                mma16816(acc[mf][nf], aF[mf], &bF[nf * 2]);
    }

#pragma unroll
    for (int mf = 0; mf < 4; mf++) {
        const int rl0 = wi * 64 + mf * 16 + (lane >> 2);
#pragma unroll
        for (int hh = 0; hh < 2; hh++) {
            const int rl = rl0 + hh * 8;
            float* dst = &g_h[(i0 + rl) * 128];
#pragma unroll
            for (int nf = 0; nf < 4; nf++) {
                const int o = obase + nf * 8 + (lane & 3) * 2;
                float2 r;
                r.x = acc[mf][nf][hh * 2 + 0];
                r.y = acc[mf][nf][hh * 2 + 1];
                *(float2*)&dst[o] = r;
            }
        }
    }
}

// ---------------------------------------------------------------------------
// K1b: transpose h -> [b][o][j], convert to fp16
// ---------------------------------------------------------------------------
__global__ __launch_bounds__(256) void k1b_split() {
    __shared__ float t[32][33];
    const int b = blockIdx.z;
    const int j0 = blockIdx.x * 32, o0 = blockIdx.y * 32;
    const int tx = threadIdx.x, ty = threadIdx.y;  // 32 x 8
#pragma unroll
    for (int r = 0; r < 32; r += 8)
        t[ty + r][tx] = g_h[((size_t)b * 2048 + j0 + ty + r) * 128 + o0 + tx];
    __syncthreads();
#pragma unroll
    for (int r = 0; r < 32; r += 8) {
        float v = t[tx][ty + r];
        size_t idx = ((size_t)b * 128 + o0 + ty + r) * 2048 + j0 + tx;
        g_hT[idx] = __float2half_rn(v);
    }
}

// ---------------------------------------------------------------------------
// K2: s_src / s_dst
// ---------------------------------------------------------------------------
__global__ __launch_bounds__(256) void k2_s(const float* __restrict__ a) {
    const int warp = threadIdx.x >> 5, lane = threadIdx.x & 31;
    const int row = blockIdx.x * 8 + warp;
    const float* h = &g_h[(size_t)row * 128];
    float s1 = 0.f, s2 = 0.f;
#pragma unroll
    for (int t = 0; t < 4; t++) {
        float hv = h[lane + 32 * t];
        s1 += hv * a[lane + 32 * t];
        s2 += hv * a[128 + lane + 32 * t];
    }
#pragma unroll
    for (int off = 16; off > 0; off >>= 1) {
        s1 += __shfl_xor_sync(0xffffffffu, s1, off);
        s2 += __shfl_xor_sync(0xffffffffu, s2, off);
    }
    if (lane == 0) { g_ssrc[row] = s1; g_sdst[row] = s2; }
}

// ---------------------------------------------------------------------------
// K3: rank sort — 512 thr: 4 j per thread-group, 16 chunks of 128, float4 LDS
// ---------------------------------------------------------------------------
__global__ __launch_bounds__(512) void k3_sort() {
    __shared__ float s[2048];
    __shared__ int part[16][128];
    const int b = blockIdx.y;
    const int tid = threadIdx.x;  // 512
    for (int idx = tid; idx < 2048; idx += 512) s[idx] = g_sdst[b * 2048 + idx];
    __syncthreads();
    const int g = tid & 31;
    const int ck = tid >> 5;
    const int jl0 = g * 4;
    const int jg0 = blockIdx.x * 128 + jl0;
    const float4 my = *(const float4*)&s[jg0];
    int r0 = 0, r1 = 0, r2 = 0, r3 = 0;
    const int q0 = ck * 128;
#pragma unroll 8
    for (int q = q0; q < q0 + 128; q += 4) {
        const float4 v = *(const float4*)&s[q];
        r0 += (v.x < my.x) || (v.x == my.x && (q + 0) < (jg0 + 0));
        r1 += (v.x < my.y) || (v.x == my.y && (q + 0) < (jg0 + 1));
        r2 += (v.x < my.z) || (v.x == my.z && (q + 0) < (jg0 + 2));
        r3 += (v.x < my.w) || (v.x == my.w && (q + 0) < (jg0 + 3));
        r0 += (v.y < my.x) || (v.y == my.x && (q + 1) < (jg0 + 0));
        r1 += (v.y < my.y) || (v.y == my.y && (q + 1) < (jg0 + 1));
        r2 += (v.y < my.z) || (v.y == my.z && (q + 1) < (jg0 + 2));
        r3 += (v.y < my.w) || (v.y == my.w && (q + 1) < (jg0 + 3));
        r0 += (v.z < my.x) || (v.z == my.x && (q + 2) < (jg0 + 0));
        r1 += (v.z < my.y) || (v.z == my.y && (q + 2) < (jg0 + 1));
        r2 += (v.z < my.z) || (v.z == my.z && (q + 2) < (jg0 + 2));
        r3 += (v.z < my.w) || (v.z == my.w && (q + 2) < (jg0 + 3));
        r0 += (v.w < my.x) || (v.w == my.x && (q + 3) < (jg0 + 0));
        r1 += (v.w < my.y) || (v.w == my.y && (q + 3) < (jg0 + 1));
        r2 += (v.w < my.z) || (v.w == my.z && (q + 3) < (jg0 + 2));
        r3 += (v.w < my.w) || (v.w == my.w && (q + 3) < (jg0 + 3));
    }
    part[ck][jl0 + 0] = r0; part[ck][jl0 + 1] = r1;
    part[ck][jl0 + 2] = r2; part[ck][jl0 + 3] = r3;
    __syncthreads();
    if (tid < 128) {
        int r = 0;
#pragma unroll
        for (int c = 0; c < 16; c++) r += part[c][tid];
        const float mv = s[blockIdx.x * 128 + tid];
        const int base = b * 2048;
        g_v[base + r]    = mv;
        g_perm[base + r] = blockIdx.x * 128 + tid;
        g_w1[base + r]   = expf(mv);
        g_w02[base + r]  = expf(SLOPE * mv);
    }
}

// ---------------------------------------------------------------------------
// K4: fp32 chunked scans for numerator tables (grid (4,8), 1024 thr)
// ---------------------------------------------------------------------------
__global__ __launch_bounds__(1024) void k4_scanE() {
    __shared__ float cs1[32][33], cs02[32][33];
    __shared__ float off1A[32][32], off02A[32][32];
    __shared__ float tot1s[32];
    const int b = blockIdx.y;
    const int ol = threadIdx.x & 31;
    const int o = blockIdx.x * 32 + ol;
    const int c = threadIdx.x >> 5;
    const int base = b * 2048;
    const int r0 = c * 64;

    float a1 = 0.f, a02 = 0.f;
    for (int r = r0; r < r0 + 64; r++) {
        int j = g_perm[base + r];
        float hv = g_h[((size_t)(base + j)) * 128 + o];
        a1  += g_w1[base + r]  * hv;
        a02 += g_w02[base + r] * hv;
    }
    cs1[c][ol] = a1; cs02[c][ol] = a02;
    __syncthreads();
    if (c == 0) {
        float r1 = 0.f, r2 = 0.f;
        for (int q = 0; q < 32; q++) {
            off1A[q][ol] = r1;  r1 += cs1[q][ol];
            off02A[q][ol] = r2; r2 += cs02[q][ol];
        }
        tot1s[ol] = r1;
    }
    __syncthreads();
    float run1 = off1A[c][ol], run02 = off02A[c][ol];
    const float tot1 = tot1s[ol];
    const size_t tbase = ((size_t)b * 2049) * 128 + o;
    for (int r = r0; r < r0 + 64; r++) {
        int j = g_perm[base + r];
        float hv = g_h[((size_t)(base + j)) * 128 + o];
        g_suf1[tbase + (size_t)r * 128]  = tot1 - run1;
        run1 += g_w1[base + r] * hv;
        g_pre02[tbase + (size_t)r * 128] = run02;
        run02 += g_w02[base + r] * hv;
    }
    if (c == 31) {
        g_suf1[tbase + (size_t)2048 * 128]  = 0.f;
        g_pre02[tbase + (size_t)2048 * 128] = run02;
    }
}

// K4b: denominators (tiny, fp64)
__global__ __launch_bounds__(32) void k4b_scanD() {
    __shared__ double cs1[16], cs02[16], off1[16], off02[16], tot[2];
    const int b = blockIdx.x;
    const int c = threadIdx.x;
    const int base = b * 2048;
    if (c < 16) {
        double a1 = 0.0, a02 = 0.0;
        for (int r = c * 128; r < c * 128 + 128; r++) {
            a1 += (double)g_w1[base + r]; a02 += (double)g_w02[base + r];
        }
        cs1[c] = a1; cs02[c] = a02;
    }
    __syncthreads();
    if (c == 0) {
        double r1 = 0.0, r2 = 0.0;
        for (int q = 0; q < 16; q++) {
            off1[q] = r1; r1 += cs1[q];
            off02[q] = r2; r2 += cs02[q];
        }
        tot[0] = r1; tot[1] = r2;
    }
    __syncthreads();
    if (c < 16) {
        double run1 = off1[c], run02 = off02[c], t1 = tot[0];
        const size_t tb = (size_t)b * 2049;
        for (int r = c * 128; r < c * 128 + 128; r++) {
            g_sufD1[tb + r] = (float)(t1 - run1);
            run1 += (double)g_w1[base + r];
            g_preD02[tb + r] = (float)run02;
            run02 += (double)g_w02[base + r];
        }
        if (c == 15) { g_sufD1[tb + 2048] = 0.f; g_preD02[tb + 2048] = (float)run02; }
    }
}

// ---------------------------------------------------------------------------
// K5: fp16 mma.sync GEMM (adj@h) + attention epilogue + lrelu
// 512 thr, 16 warps = 4(i) x 4(o), warp 32x32. CTA 128x128, K-chunk 128.
// All-register double buffering: LDG (A fp32 + B fp16) early, STS.128 late,
// ONE barrier per chunk (cp.async dropped — LDGSTS rt=8 > LDG+STS.128).
// ---------------------------------------------------------------------------
#define TILE_BYTES (128u * AROW)     // 34816
#define OFF_A 0u
#define OFF_B TILE_BYTES
#define STG_BYTES (2u * TILE_BYTES)  // 69632
#define K5_SMEM (2u * STG_BYTES)     // 139264

__global__ __launch_bounds__(512) void k5_main(const float* __restrict__ adj,
                                               float* __restrict__ out) {
    extern __shared__ __align__(128) char dsm[];
    __shared__ int kS[128];
    __shared__ float e1S[128], e02S[128], dinvS[128];
    const uint32_t sb = smem_u32(dsm);
    const int tid = threadIdx.x;
    const int b = blockIdx.y;
    const int i0 = blockIdx.x * 128;

    // --- binary-search setup (uses dynamic smem as temp before tiles) ---
    {
        float* vS = (float*)dsm;
        for (int idx = tid; idx < 2048; idx += 512) vS[idx] = g_v[b * 2048 + idx];
        __syncthreads();
        if (tid < 128) {
            float si = g_ssrc[b * 2048 + i0 + tid];
            float target = -si;
            int lo = 0, hi = 2048;
            while (lo < hi) { int mid = (lo + hi) >> 1; if (vS[mid] < target) lo = mid + 1; else hi = mid; }
            float e1 = expf(si), e02 = expf(SLOPE * si);
            float Dv = e1 * g_sufD1[(size_t)b * 2049 + lo] + e02 * g_preD02[(size_t)b * 2049 + lo];
            kS[tid] = lo; e1S[tid] = e1; e02S[tid] = e02; dinvS[tid] = 1.0f / Dv;
        }
        __syncthreads();
    }

    const int warp = tid >> 5, lane = tid & 31;

    // A loader: 4 passes; row = p*32 + warp*2 + (lane>>4); 32B fp32 per thread
    const float* adjT = adj + ((size_t)(b * 2048 + i0)) * 2048;
    const int aRowOff = warp * 2 + (lane >> 4);         // + p*32
    const int aCol = (lane & 15) * 8;                   // float index
    const uint32_t aSts = (uint32_t)aRowOff * AROW + (uint32_t)aCol * 2;  // + p*32*AROW
    // B loader: 4 passes; idx = p*512+tid: brow = idx>>4, seg = idx&15
    const __half* hTb = g_hT + ((size_t)b * 128) * 2048;
    const int bRow = tid >> 4, bSeg = tid & 15;         // row + p*32
    const uint32_t bSts = (uint32_t)bRow * AROW + (uint32_t)bSeg * 16;    // + p*32*AROW

    // compute mapping: warp -> (wi 0..3, wo 0..3)
    const int wi = warp & 3, wo = warp >> 2;
    const int obase = wo * 32;
    const uint32_t aLane = (uint32_t)(wi * 32 + (lane & 15)) * AROW + ((lane >> 4) << 4);
    const uint32_t bLane = (uint32_t)(obase + (lane & 7) + ((lane & 16) >> 1)) * AROW + ((lane & 8) << 1);

    float acc[2][4][4];
#pragma unroll
    for (int mf = 0; mf < 2; mf++)
#pragma unroll
        for (int nf = 0; nf < 4; nf++)
#pragma unroll
            for (int e = 0; e < 4; e++) acc[mf][nf][e] = 0.f;

    // ---- prologue: chunk 0 -> stage 0 ----
    {
#pragma unroll
        for (int p = 0; p < 4; p++) {
            const float* src = adjT + (size_t)(p * 32 + aRowOff) * 2048 + aCol;
            float4 u = *(const float4*)src;
            float4 w = *(const float4*)(src + 4);
            sts128(sb + OFF_A + aSts + (uint32_t)p * (32u * AROW),
                   cvt2h(u.y, u.x), cvt2h(u.w, u.z), cvt2h(w.y, w.x), cvt2h(w.w, w.z));
        }
#pragma unroll
        for (int p = 0; p < 4; p++) {
            uint4 v = *(const uint4*)(hTb + (size_t)(p * 32 + bRow) * 2048 + bSeg * 8);
            sts128(sb + OFF_B + bSts + (uint32_t)p * (32u * AROW), v.x, v.y, v.z, v.w);
        }
        __syncthreads();
    }

    for (int c = 0; c < 16; c++) {
        const uint32_t sCur = sb + (c & 1 ? STG_BYTES : 0u);
        const uint32_t sNxt = sb + (c & 1 ? 0u : STG_BYTES);
        const int j1 = (c + 1) * 128;
        float4 fA[8];
        uint4 fB[4];
        if (c < 15) {
#pragma unroll
            for (int p = 0; p < 4; p++) {
                const float* src = adjT + (size_t)(p * 32 + aRowOff) * 2048 + j1 + aCol;
                fA[p * 2]     = *(const float4*)src;
                fA[p * 2 + 1] = *(const float4*)(src + 4);
            }
#pragma unroll
            for (int p = 0; p < 4; p++)
                fB[p] = *(const uint4*)(hTb + (size_t)(p * 32 + bRow) * 2048 + j1 + bSeg * 8);
        }
        // ---- compute current chunk: 8 k16 steps ----
#pragma unroll
        for (int kk = 0; kk < 8; kk++) {
            uint32_t aF[2][4], bF[8];
            const uint32_t aAddr = sCur + OFF_A + aLane + kk * 32;
            const uint32_t bAddr = sCur + OFF_B + bLane + kk * 32;
            ldmx4(aF[0], aAddr);
            ldmx4(aF[1], aAddr + 16u * AROW);
            ldmx4(&bF[0], bAddr);
            ldmx4(&bF[4], bAddr + 16u * AROW);
#pragma unroll
            for (int mf = 0; mf < 2; mf++)
#pragma unroll
                for (int nf = 0; nf < 4; nf++)
                    mma16816(acc[mf][nf], aF[mf], &bF[nf * 2]);
        }
        if (c < 15) {
#pragma unroll
            for (int p = 0; p < 4; p++) {
                float4 u = fA[p * 2], w = fA[p * 2 + 1];
                sts128(sNxt + OFF_A + aSts + (uint32_t)p * (32u * AROW),
                       cvt2h(u.y, u.x), cvt2h(u.w, u.z), cvt2h(w.y, w.x), cvt2h(w.w, w.z));
            }
#pragma unroll
            for (int p = 0; p < 4; p++)
                sts128(sNxt + OFF_B + bSts + (uint32_t)p * (32u * AROW),
                       fB[p].x, fB[p].y, fB[p].z, fB[p].w);
        }
        __syncthreads();
    }

    // ---- epilogue: attention lookup + lrelu + store ----
#pragma unroll
    for (int mf = 0; mf < 2; mf++) {
        const int rl0 = wi * 32 + mf * 16 + (lane >> 2);
#pragma unroll
        for (int hh = 0; hh < 2; hh++) {
            const int rl = rl0 + hh * 8;
            const int k = kS[rl];
            const float e1 = e1S[rl], e02 = e02S[rl], dinv = dinvS[rl];
            const float* suf = &g_suf1[((size_t)(b * 2049 + k)) * 128];
            const float* pre = &g_pre02[((size_t)(b * 2049 + k)) * 128];
            float* dst = &out[((size_t)(b * 2048 + i0 + rl)) * 128];
#pragma unroll
            for (int nf = 0; nf < 4; nf++) {
                const int o = obase + nf * 8 + (lane & 3) * 2;
                float2 sf = *(const float2*)&suf[o];
                float2 pf = *(const float2*)&pre[o];
                float v0 = acc[mf][nf][hh * 2 + 0] + (e1 * sf.x + e02 * pf.x) * dinv;
                float v1 = acc[mf][nf][hh * 2 + 1] + (e1 * sf.y + e02 * pf.y) * dinv;
                float2 r;
                r.x = v0 >= 0.f ? v0 : SLOPE * v0;
                r.y = v1 >= 0.f ? v1 : SLOPE * v1;
                *(float2*)&dst[o] = r;
            }
        }
    }
}

// ---------------------------------------------------------------------------
extern "C" void kernel_launch(void* const* d_in, const int* in_sizes, int n_in,
                              void* d_out, int out_size) {
    (void)in_sizes; (void)n_in; (void)out_size;
    const float* x   = (const float*)d_in[0];
    const float* adj = (const float*)d_in[1];
    const float* W   = (const float*)d_in[2];
    const float* a   = (const float*)d_in[3];
    float* out = (float*)d_out;

    cudaFuncSetAttribute(k1_mma, cudaFuncAttributeMaxDynamicSharedMemorySize, K1_SMEM);
    cudaFuncSetAttribute(k5_main, cudaFuncAttributeMaxDynamicSharedMemorySize, K5_SMEM);

    k0_wt<<<dim3(4, 4), dim3(32, 8)>>>(W);
    k1_mma<<<128, 256, K1_SMEM>>>(x);
    k1b_split<<<dim3(64, 4, 8), dim3(32, 8)>>>();
    k2_s<<<2048, 256>>>(a);
    k3_sort<<<dim3(16, 8), 512>>>();
    k4_scanE<<<dim3(4, 8), 1024>>>();
    k4b_scanD<<<8, 32>>>();
    k5_main<<<dim3(16, 8), 512, K5_SMEM>>>(adj, out);
}

// round 13
// speedup vs baseline: 2.4453x; 1.1253x over previous
#include <cuda_runtime.h>
#include <cuda_fp16.h>
#include <math.h>
#include <stdint.h>

#define SLOPE 0.2f
#define AROW 272u

// Shapes fixed: B=8, N=2048, D=128.
__device__ float g_h[8 * 2048 * 128];     // h = x @ W (fp32)
__device__ __half g_hT[8 * 128 * 2048];   // fp16 h, transposed [b][o][j]
__device__ __half g_WT[128 * 128];        // fp16 W^T [o][k]
__device__ float g_ssrc[8 * 2048];
__device__ float g_sdst[8 * 2048];
__device__ float g_v[8 * 2048];
__device__ int   g_perm[8 * 2048];
__device__ float g_w1[8 * 2048];
__device__ float g_w02[8 * 2048];
__device__ float g_suf1[8 * 2049 * 128];
__device__ float g_pre02[8 * 2049 * 128];
__device__ float g_sufD1[8 * 2049];
__device__ float g_preD02[8 * 2049];
__device__ float g_cs1[8 * 32 * 128];     // chunk sums (k4 phase A)
__device__ float g_cs02[8 * 32 * 128];

// ---------------------------------------------------------------------------
// helpers
// ---------------------------------------------------------------------------
__device__ __forceinline__ uint32_t smem_u32(const void* p) {
    uint32_t a;
    asm("{ .reg .u64 t; cvta.to.shared.u64 t, %1; cvt.u32.u64 %0, t; }" : "=r"(a) : "l"(p));
    return a;
}
__device__ __forceinline__ void ldmx4(uint32_t* r, uint32_t addr) {
    asm volatile("ldmatrix.sync.aligned.m8n8.x4.shared.b16 {%0,%1,%2,%3}, [%4];"
                 : "=r"(r[0]), "=r"(r[1]), "=r"(r[2]), "=r"(r[3]) : "r"(addr));
}
__device__ __forceinline__ void mma16816(float* d, const uint32_t* a, const uint32_t* b) {
    asm volatile(
        "mma.sync.aligned.m16n8k16.row.col.f32.f16.f16.f32 "
        "{%0,%1,%2,%3}, {%4,%5,%6,%7}, {%8,%9}, {%0,%1,%2,%3};"
        : "+f"(d[0]), "+f"(d[1]), "+f"(d[2]), "+f"(d[3])
        : "r"(a[0]), "r"(a[1]), "r"(a[2]), "r"(a[3]), "r"(b[0]), "r"(b[1]));
}
__device__ __forceinline__ uint32_t cvt2h(float hi, float lo) {
    uint32_t r;
    asm("cvt.rn.f16x2.f32 %0, %1, %2;" : "=r"(r) : "f"(hi), "f"(lo));
    return r;
}
__device__ __forceinline__ void sts128(uint32_t a, uint32_t x, uint32_t y, uint32_t z, uint32_t w) {
    asm volatile("st.shared.v4.b32 [%0], {%1,%2,%3,%4};" :: "r"(a), "r"(x), "r"(y), "r"(z), "r"(w) : "memory");
}

// ---------------------------------------------------------------------------
// K0: W [k][o] fp32 -> g_WT [o][k] fp16
// ---------------------------------------------------------------------------
__global__ __launch_bounds__(256) void k0_wt(const float* __restrict__ W) {
    __shared__ float t[32][33];
    const int k0 = blockIdx.x * 32, o0 = blockIdx.y * 32;
    const int tx = threadIdx.x, ty = threadIdx.y;
#pragma unroll
    for (int r = 0; r < 32; r += 8)
        t[ty + r][tx] = W[(size_t)(k0 + ty + r) * 128 + o0 + tx];
    __syncthreads();
#pragma unroll
    for (int r = 0; r < 32; r += 8)
        g_WT[(size_t)(o0 + ty + r) * 128 + k0 + tx] = __float2half_rn(t[tx][ty + r]);
}

// ---------------------------------------------------------------------------
// K1: h = x @ W via fp16 mma.sync + FUSED s_src/s_dst computation
// grid 128 CTAs, 256 thr = 8 warps (2 wi x 4 wo), warp 64x32
// ---------------------------------------------------------------------------
#define K1_TILE (128u * AROW)
#define K1_SMEM (2u * K1_TILE)

__global__ __launch_bounds__(256) void k1_mma(const float* __restrict__ x,
                                              const float* __restrict__ a) {
    extern __shared__ __align__(128) char dsm[];
    __shared__ float aS[256];
    __shared__ float sPS[4][128], sPD[4][128];
    const uint32_t sb = smem_u32(dsm);
    const uint32_t OFF_X = 0u, OFF_W = K1_TILE;
    const int tid = threadIdx.x;
    const size_t i0 = (size_t)blockIdx.x * 128;

    aS[tid] = a[tid];

    // load WT (32KB fp16) -> SMEM [o][k]
#pragma unroll
    for (int p = 0; p < 8; p++) {
        int idx = p * 256 + tid;
        int brow = idx >> 4, seg = idx & 15;
        uint4 v = *(const uint4*)(g_WT + (size_t)brow * 128 + seg * 8);
        sts128(sb + OFF_W + (uint32_t)brow * AROW + (uint32_t)seg * 16, v.x, v.y, v.z, v.w);
    }
    // load x tile (128x128 fp32) -> cvt fp16 -> SMEM
    {
        const int row = tid >> 1, half = tid & 1;
        const float* xr = x + (i0 + row) * 128 + half * 64;
        const uint32_t sBase = sb + OFF_X + (uint32_t)row * AROW + (uint32_t)half * 128;
#pragma unroll
        for (int p = 0; p < 8; p++) {
            float4 u = *(const float4*)(xr + p * 8);
            float4 w = *(const float4*)(xr + p * 8 + 4);
            sts128(sBase + p * 16, cvt2h(u.y, u.x), cvt2h(u.w, u.z),
                   cvt2h(w.y, w.x), cvt2h(w.w, w.z));
        }
    }
    __syncthreads();

    const int warp = tid >> 5, lane = tid & 31;
    const int wi = warp & 1, wo = warp >> 1;
    const int obase = wo * 32;
    const uint32_t aLane = (uint32_t)(wi * 64 + (lane & 15)) * AROW + ((lane >> 4) << 4);
    const uint32_t bLane = (uint32_t)(obase + (lane & 7) + ((lane & 16) >> 1)) * AROW + ((lane & 8) << 1);

    float acc[4][4][4];
#pragma unroll
    for (int mf = 0; mf < 4; mf++)
#pragma unroll
        for (int nf = 0; nf < 4; nf++)
#pragma unroll
            for (int e = 0; e < 4; e++) acc[mf][nf][e] = 0.f;

#pragma unroll
    for (int kk = 0; kk < 8; kk++) {
        uint32_t aF[4][4], bF[8];
        const uint32_t aAddr = sb + OFF_X + aLane + kk * 32;
        const uint32_t bAddr = sb + OFF_W + bLane + kk * 32;
#pragma unroll
        for (int mf = 0; mf < 4; mf++) ldmx4(aF[mf], aAddr + (uint32_t)mf * (16u * AROW));
        ldmx4(&bF[0], bAddr);
        ldmx4(&bF[4], bAddr + 16u * AROW);
#pragma unroll
        for (int mf = 0; mf < 4; mf++)
#pragma unroll
            for (int nf = 0; nf < 4; nf++)
                mma16816(acc[mf][nf], aF[mf], &bF[nf * 2]);
    }

    // epilogue: store h + fused s partial dots
#pragma unroll
    for (int mf = 0; mf < 4; mf++) {
#pragma unroll
        for (int hh = 0; hh < 2; hh++) {
            const int rl = wi * 64 + mf * 16 + hh * 8 + (lane >> 2);
            float* dst = &g_h[(i0 + rl) * 128];
            float p1 = 0.f, p2 = 0.f;
#pragma unroll
            for (int nf = 0; nf < 4; nf++) {
                const int o = obase + nf * 8 + (lane & 3) * 2;
                float v0 = acc[mf][nf][hh * 2 + 0];
                float v1 = acc[mf][nf][hh * 2 + 1];
                float2 r; r.x = v0; r.y = v1;
                *(float2*)&dst[o] = r;
                p1 += v0 * aS[o] + v1 * aS[o + 1];
                p2 += v0 * aS[128 + o] + v1 * aS[128 + o + 1];
            }
            p1 += __shfl_xor_sync(0xffffffffu, p1, 1);
            p1 += __shfl_xor_sync(0xffffffffu, p1, 2);
            p2 += __shfl_xor_sync(0xffffffffu, p2, 1);
            p2 += __shfl_xor_sync(0xffffffffu, p2, 2);
            if ((lane & 3) == 0) { sPS[wo][rl] = p1; sPD[wo][rl] = p2; }
        }
    }
    __syncthreads();
    if (tid < 128) {
        float s1 = sPS[0][tid] + sPS[1][tid] + sPS[2][tid] + sPS[3][tid];
        float s2 = sPD[0][tid] + sPD[1][tid] + sPD[2][tid] + sPD[3][tid];
        g_ssrc[i0 + tid] = s1;
        g_sdst[i0 + tid] = s2;
    }
}

// ---------------------------------------------------------------------------
// K1b: transpose h -> [b][o][j], convert to fp16
// ---------------------------------------------------------------------------
__global__ __launch_bounds__(256) void k1b_split() {
    __shared__ float t[32][33];
    const int b = blockIdx.z;
    const int j0 = blockIdx.x * 32, o0 = blockIdx.y * 32;
    const int tx = threadIdx.x, ty = threadIdx.y;
#pragma unroll
    for (int r = 0; r < 32; r += 8)
        t[ty + r][tx] = g_h[((size_t)b * 2048 + j0 + ty + r) * 128 + o0 + tx];
    __syncthreads();
#pragma unroll
    for (int r = 0; r < 32; r += 8) {
        float v = t[tx][ty + r];
        size_t idx = ((size_t)b * 128 + o0 + ty + r) * 2048 + j0 + tx;
        g_hT[idx] = __float2half_rn(v);
    }
}

// ---------------------------------------------------------------------------
// K3: rank sort — 512 thr: 4 j per thread-group, 16 chunks of 128, float4 LDS
// ---------------------------------------------------------------------------
__global__ __launch_bounds__(512) void k3_sort() {
    __shared__ float s[2048];
    __shared__ int part[16][128];
    const int b = blockIdx.y;
    const int tid = threadIdx.x;
    for (int idx = tid; idx < 2048; idx += 512) s[idx] = g_sdst[b * 2048 + idx];
    __syncthreads();
    const int g = tid & 31;
    const int ck = tid >> 5;
    const int jl0 = g * 4;
    const int jg0 = blockIdx.x * 128 + jl0;
    const float4 my = *(const float4*)&s[jg0];
    int r0 = 0, r1 = 0, r2 = 0, r3 = 0;
    const int q0 = ck * 128;
#pragma unroll 8
    for (int q = q0; q < q0 + 128; q += 4) {
        const float4 v = *(const float4*)&s[q];
        r0 += (v.x < my.x) || (v.x == my.x && (q + 0) < (jg0 + 0));
        r1 += (v.x < my.y) || (v.x == my.y && (q + 0) < (jg0 + 1));
        r2 += (v.x < my.z) || (v.x == my.z && (q + 0) < (jg0 + 2));
        r3 += (v.x < my.w) || (v.x == my.w && (q + 0) < (jg0 + 3));
        r0 += (v.y < my.x) || (v.y == my.x && (q + 1) < (jg0 + 0));
        r1 += (v.y < my.y) || (v.y == my.y && (q + 1) < (jg0 + 1));
        r2 += (v.y < my.z) || (v.y == my.z && (q + 1) < (jg0 + 2));
        r3 += (v.y < my.w) || (v.y == my.w && (q + 1) < (jg0 + 3));
        r0 += (v.z < my.x) || (v.z == my.x && (q + 2) < (jg0 + 0));
        r1 += (v.z < my.y) || (v.z == my.y && (q + 2) < (jg0 + 1));
        r2 += (v.z < my.z) || (v.z == my.z && (q + 2) < (jg0 + 2));
        r3 += (v.z < my.w) || (v.z == my.w && (q + 2) < (jg0 + 3));
        r0 += (v.w < my.x) || (v.w == my.x && (q + 3) < (jg0 + 0));
        r1 += (v.w < my.y) || (v.w == my.y && (q + 3) < (jg0 + 1));
        r2 += (v.w < my.z) || (v.w == my.z && (q + 3) < (jg0 + 2));
        r3 += (v.w < my.w) || (v.w == my.w && (q + 3) < (jg0 + 3));
    }
    part[ck][jl0 + 0] = r0; part[ck][jl0 + 1] = r1;
    part[ck][jl0 + 2] = r2; part[ck][jl0 + 3] = r3;
    __syncthreads();
    if (tid < 128) {
        int r = 0;
#pragma unroll
        for (int c = 0; c < 16; c++) r += part[c][tid];
        const float mv = s[blockIdx.x * 128 + tid];
        const int base = b * 2048;
        g_v[base + r]    = mv;
        g_perm[base + r] = blockIdx.x * 128 + tid;
        g_w1[base + r]   = expf(mv);
        g_w02[base + r]  = expf(SLOPE * mv);
    }
}

// ---------------------------------------------------------------------------
// K4a: chunk sums — grid (4, 8, 32), 256 thr (32 o x 8 row-subchunks)
// ---------------------------------------------------------------------------
__global__ __launch_bounds__(256) void k4a_sums() {
    __shared__ float s1[8][33], s02[8][33];
    const int ol = threadIdx.x & 31, rs = threadIdx.x >> 5;
    const int o = blockIdx.x * 32 + ol;
    const int b = blockIdx.y, c = blockIdx.z;
    const int base = b * 2048;
    const int r0 = c * 64 + rs * 8;
    float a1 = 0.f, a02 = 0.f;
#pragma unroll
    for (int r = r0; r < r0 + 8; r++) {
        int j = g_perm[base + r];
        float hv = g_h[((size_t)(base + j)) * 128 + o];
        a1  += g_w1[base + r]  * hv;
        a02 += g_w02[base + r] * hv;
    }
    s1[rs][ol] = a1; s02[rs][ol] = a02;
    __syncthreads();
    if (rs == 0) {
        float t1 = 0.f, t02 = 0.f;
#pragma unroll
        for (int q = 0; q < 8; q++) { t1 += s1[q][ol]; t02 += s02[q][ol]; }
        g_cs1[(b * 32 + c) * 128 + o]  = t1;
        g_cs02[(b * 32 + c) * 128 + o] = t02;
    }
}

// ---------------------------------------------------------------------------
// K4b: scan + table write — grid (4, 8, 32), 256 thr
// ---------------------------------------------------------------------------
__global__ __launch_bounds__(256) void k4b_scan() {
    __shared__ float s1[8][33], s02[8][33];
    const int ol = threadIdx.x & 31, rs = threadIdx.x >> 5;
    const int o = blockIdx.x * 32 + ol;
    const int b = blockIdx.y, c = blockIdx.z;
    const int base = b * 2048;

    float off1 = 0.f, off02 = 0.f, tot1 = 0.f;
#pragma unroll
    for (int q = 0; q < 32; q++) {
        float v1  = g_cs1[(b * 32 + q) * 128 + o];
        float v02 = g_cs02[(b * 32 + q) * 128 + o];
        tot1 += v1;
        if (q < c) { off1 += v1; off02 += v02; }
    }
    const int r0 = c * 64 + rs * 8;
    float a1 = 0.f, a02 = 0.f;
#pragma unroll
    for (int r = r0; r < r0 + 8; r++) {
        int j = g_perm[base + r];
        float hv = g_h[((size_t)(base + j)) * 128 + o];
        a1  += g_w1[base + r]  * hv;
        a02 += g_w02[base + r] * hv;
    }
    s1[rs][ol] = a1; s02[rs][ol] = a02;
    __syncthreads();
    float run1 = off1, run02 = off02;
    for (int q = 0; q < rs; q++) { run1 += s1[q][ol]; run02 += s02[q][ol]; }
    const size_t tbase = ((size_t)b * 2049) * 128 + o;
#pragma unroll
    for (int r = r0; r < r0 + 8; r++) {
        int j = g_perm[base + r];
        float hv = g_h[((size_t)(base + j)) * 128 + o];
        g_suf1[tbase + (size_t)r * 128]  = tot1 - run1;
        run1 += g_w1[base + r] * hv;
        g_pre02[tbase + (size_t)r * 128] = run02;
        run02 += g_w02[base + r] * hv;
    }
    if (c == 31 && rs == 7) {
        g_suf1[tbase + (size_t)2048 * 128]  = 0.f;
        g_pre02[tbase + (size_t)2048 * 128] = run02;
    }
}

// K4d: denominators (tiny, fp64)
__global__ __launch_bounds__(32) void k4d_scanD() {
    __shared__ double cs1[16], cs02[16], off1[16], off02[16], tot[2];
    const int b = blockIdx.x;
    const int c = threadIdx.x;
    const int base = b * 2048;
    if (c < 16) {
        double a1 = 0.0, a02 = 0.0;
        for (int r = c * 128; r < c * 128 + 128; r++) {
            a1 += (double)g_w1[base + r]; a02 += (double)g_w02[base + r];
        }
        cs1[c] = a1; cs02[c] = a02;
    }
    __syncthreads();
    if (c == 0) {
        double r1 = 0.0, r2 = 0.0;
        for (int q = 0; q < 16; q++) {
            off1[q] = r1; r1 += cs1[q];
            off02[q] = r2; r2 += cs02[q];
        }
        tot[0] = r1; tot[1] = r2;
    }
    __syncthreads();
    if (c < 16) {
        double run1 = off1[c], run02 = off02[c], t1 = tot[0];
        const size_t tb = (size_t)b * 2049;
        for (int r = c * 128; r < c * 128 + 128; r++) {
            g_sufD1[tb + r] = (float)(t1 - run1);
            run1 += (double)g_w1[base + r];
            g_preD02[tb + r] = (float)run02;
            run02 += (double)g_w02[base + r];
        }
        if (c == 15) { g_sufD1[tb + 2048] = 0.f; g_preD02[tb + 2048] = (float)run02; }
    }
}

// ---------------------------------------------------------------------------
// K5: fp16 mma.sync GEMM (adj@h) + attention epilogue + lrelu (as R12)
// ---------------------------------------------------------------------------
#define TILE_BYTES (128u * AROW)
#define OFF_A 0u
#define OFF_B TILE_BYTES
#define STG_BYTES (2u * TILE_BYTES)
#define K5_SMEM (2u * STG_BYTES)

__global__ __launch_bounds__(512) void k5_main(const float* __restrict__ adj,
                                               float* __restrict__ out) {
    extern __shared__ __align__(128) char dsm[];
    __shared__ int kS[128];
    __shared__ float e1S[128], e02S[128], dinvS[128];
    const uint32_t sb = smem_u32(dsm);
    const int tid = threadIdx.x;
    const int b = blockIdx.y;
    const int i0 = blockIdx.x * 128;

    {
        float* vS = (float*)dsm;
        for (int idx = tid; idx < 2048; idx += 512) vS[idx] = g_v[b * 2048 + idx];
        __syncthreads();
        if (tid < 128) {
            float si = g_ssrc[b * 2048 + i0 + tid];
            float target = -si;
            int lo = 0, hi = 2048;
            while (lo < hi) { int mid = (lo + hi) >> 1; if (vS[mid] < target) lo = mid + 1; else hi = mid; }
            float e1 = expf(si), e02 = expf(SLOPE * si);
            float Dv = e1 * g_sufD1[(size_t)b * 2049 + lo] + e02 * g_preD02[(size_t)b * 2049 + lo];
            kS[tid] = lo; e1S[tid] = e1; e02S[tid] = e02; dinvS[tid] = 1.0f / Dv;
        }
        __syncthreads();
    }

    const int warp = tid >> 5, lane = tid & 31;

    const float* adjT = adj + ((size_t)(b * 2048 + i0)) * 2048;
    const int aRowOff = warp * 2 + (lane >> 4);
    const int aCol = (lane & 15) * 8;
    const uint32_t aSts = (uint32_t)aRowOff * AROW + (uint32_t)aCol * 2;
    const __half* hTb = g_hT + ((size_t)b * 128) * 2048;
    const int bRow = tid >> 4, bSeg = tid & 15;
    const uint32_t bSts = (uint32_t)bRow * AROW + (uint32_t)bSeg * 16;

    const int wi = warp & 3, wo = warp >> 2;
    const int obase = wo * 32;
    const uint32_t aLane = (uint32_t)(wi * 32 + (lane & 15)) * AROW + ((lane >> 4) << 4);
    const uint32_t bLane = (uint32_t)(obase + (lane & 7) + ((lane & 16) >> 1)) * AROW + ((lane & 8) << 1);

    float acc[2][4][4];
#pragma unroll
    for (int mf = 0; mf < 2; mf++)
#pragma unroll
        for (int nf = 0; nf < 4; nf++)
#pragma unroll
            for (int e = 0; e < 4; e++) acc[mf][nf][e] = 0.f;

    {
#pragma unroll
        for (int p = 0; p < 4; p++) {
            const float* src = adjT + (size_t)(p * 32 + aRowOff) * 2048 + aCol;
            float4 u = *(const float4*)src;
            float4 w = *(const float4*)(src + 4);
            sts128(sb + OFF_A + aSts + (uint32_t)p * (32u * AROW),
                   cvt2h(u.y, u.x), cvt2h(u.w, u.z), cvt2h(w.y, w.x), cvt2h(w.w, w.z));
        }
#pragma unroll
        for (int p = 0; p < 4; p++) {
            uint4 v = *(const uint4*)(hTb + (size_t)(p * 32 + bRow) * 2048 + bSeg * 8);
            sts128(sb + OFF_B + bSts + (uint32_t)p * (32u * AROW), v.x, v.y, v.z, v.w);
        }
        __syncthreads();
    }

    for (int c = 0; c < 16; c++) {
        const uint32_t sCur = sb + (c & 1 ? STG_BYTES : 0u);
        const uint32_t sNxt = sb + (c & 1 ? 0u : STG_BYTES);
        const int j1 = (c + 1) * 128;
        float4 fA[8];
        uint4 fB[4];
        if (c < 15) {
#pragma unroll
            for (int p = 0; p < 4; p++) {
                const float* src = adjT + (size_t)(p * 32 + aRowOff) * 2048 + j1 + aCol;
                fA[p * 2]     = *(const float4*)src;
                fA[p * 2 + 1] = *(const float4*)(src + 4);
            }
#pragma unroll
            for (int p = 0; p < 4; p++)
                fB[p] = *(const uint4*)(hTb + (size_t)(p * 32 + bRow) * 2048 + j1 + bSeg * 8);
        }
#pragma unroll
        for (int kk = 0; kk < 8; kk++) {
            uint32_t aF[2][4], bF[8];
            const uint32_t aAddr = sCur + OFF_A + aLane + kk * 32;
            const uint32_t bAddr = sCur + OFF_B + bLane + kk * 32;
            ldmx4(aF[0], aAddr);
            ldmx4(aF[1], aAddr + 16u * AROW);
            ldmx4(&bF[0], bAddr);
            ldmx4(&bF[4], bAddr + 16u * AROW);
#pragma unroll
            for (int mf = 0; mf < 2; mf++)
#pragma unroll
                for (int nf = 0; nf < 4; nf++)
                    mma16816(acc[mf][nf], aF[mf], &bF[nf * 2]);
        }
        if (c < 15) {
#pragma unroll
            for (int p = 0; p < 4; p++) {
                float4 u = fA[p * 2], w = fA[p * 2 + 1];
                sts128(sNxt + OFF_A + aSts + (uint32_t)p * (32u * AROW),
                       cvt2h(u.y, u.x), cvt2h(u.w, u.z), cvt2h(w.y, w.x), cvt2h(w.w, w.z));
            }
#pragma unroll
            for (int p = 0; p < 4; p++)
                sts128(sNxt + OFF_B + bSts + (uint32_t)p * (32u * AROW),
                       fB[p].x, fB[p].y, fB[p].z, fB[p].w);
        }
        __syncthreads();
    }

#pragma unroll
    for (int mf = 0; mf < 2; mf++) {
        const int rl0 = wi * 32 + mf * 16 + (lane >> 2);
#pragma unroll
        for (int hh = 0; hh < 2; hh++) {
            const int rl = rl0 + hh * 8;
            const int k = kS[rl];
            const float e1 = e1S[rl], e02 = e02S[rl], dinv = dinvS[rl];
            const float* suf = &g_suf1[((size_t)(b * 2049 + k)) * 128];
            const float* pre = &g_pre02[((size_t)(b * 2049 + k)) * 128];
            float* dst = &out[((size_t)(b * 2048 + i0 + rl)) * 128];
#pragma unroll
            for (int nf = 0; nf < 4; nf++) {
                const int o = obase + nf * 8 + (lane & 3) * 2;
                float2 sf = *(const float2*)&suf[o];
                float2 pf = *(const float2*)&pre[o];
                float v0 = acc[mf][nf][hh * 2 + 0] + (e1 * sf.x + e02 * pf.x) * dinv;
                float v1 = acc[mf][nf][hh * 2 + 1] + (e1 * sf.y + e02 * pf.y) * dinv;
                float2 r;
                r.x = v0 >= 0.f ? v0 : SLOPE * v0;
                r.y = v1 >= 0.f ? v1 : SLOPE * v1;
                *(float2*)&dst[o] = r;
            }
        }
    }
}

// ---------------------------------------------------------------------------
extern "C" void kernel_launch(void* const* d_in, const int* in_sizes, int n_in,
                              void* d_out, int out_size) {
    (void)in_sizes; (void)n_in; (void)out_size;
    const float* x   = (const float*)d_in[0];
    const float* adj = (const float*)d_in[1];
    const float* W   = (const float*)d_in[2];
    const float* a   = (const float*)d_in[3];
    float* out = (float*)d_out;

    cudaFuncSetAttribute(k1_mma, cudaFuncAttributeMaxDynamicSharedMemorySize, K1_SMEM);
    cudaFuncSetAttribute(k5_main, cudaFuncAttributeMaxDynamicSharedMemorySize, K5_SMEM);

    k0_wt<<<dim3(4, 4), dim3(32, 8)>>>(W);
    k1_mma<<<128, 256, K1_SMEM>>>(x, a);
    k1b_split<<<dim3(64, 4, 8), dim3(32, 8)>>>();
    k3_sort<<<dim3(16, 8), 512>>>();
    k4a_sums<<<dim3(4, 8, 32), 256>>>();
    k4b_scan<<<dim3(4, 8, 32), 256>>>();
    k4d_scanD<<<8, 32>>>();
    k5_main<<<dim3(16, 8), 512, K5_SMEM>>>(adj, out);
}